// round 12
// baseline (speedup 1.0000x reference)
#include <cuda_runtime.h>
#include <cuda_bf16.h>
#include <cuda_fp16.h>
#include <cstdint>

#define NREPO 30000
#define NUSER 70000
#define NNODE 100000
#define RREL  8
#define HDIM  128
#define B1 (NUSER * RREL)
#define B2 (NREPO * RREL)
#define NB1 ((B1 + 1023) / 1024)
#define NB2 ((B2 + 1023) / 1024)
#define EMAX 1000000

// fused front kernel block ranges
#define ZBLKS ((B1 + 255) / 256)
#define MBLKS ((NREPO * HDIM + 255) / 256)
#define UBLKS (HDIM / 2)

// ---------------- scratch ----------------------------------------------------
__device__ float  g_h0[(size_t)NREPO * HDIM];
__device__ __half g_h1h[(size_t)NNODE * HDIM];
__device__ __half g_y1h[(size_t)B2 * HDIM];
__device__ float  g_uroot[HDIM];
__device__ int    g_cnt1[B1], g_off1[B1], g_cur1[B1], g_bsum1[NB1];
__device__ int    g_cnt2[B2], g_off2[B2], g_cur2[B2], g_bsum2[NB2];
__device__ int    g_perm1[EMAX];
__device__ int    g_perm2[EMAX];

// ---------------- fused front: zero counters | mlp | uroot -------------------
__global__ void front_k(const float* __restrict__ x, const float* __restrict__ mlp_w,
                        const float* __restrict__ mlp_b, const float* __restrict__ root1) {
    int bx = blockIdx.x;
    int tid = threadIdx.x;
    if (bx < ZBLKS) {
        int i = bx * 256 + tid;
        if (i < B1) g_cnt1[i] = 0;
        if (i < B2) g_cnt2[i] = 0;
        return;
    }
    bx -= ZBLKS;
    if (bx < MBLKS) {
        int g = bx * 256 + tid;
        if (g >= NREPO * HDIM) return;
        int n = g >> 7, o = g & 127;
        float acc = mlp_b[o];
#pragma unroll
        for (int k = 0; k < 8; k++)
            acc = fmaf(__ldg(&x[n * 8 + k]), __ldg(&mlp_w[k * HDIM + o]), acc);
        g_h0[g] = fmaxf(acc, 0.f);
        return;
    }
    bx -= MBLKS;
    {
        int half = tid >> 7;
        int k = tid & 127;
        int o = bx * 2 + half;
        float v = fmaxf(mlp_b[k], 0.f) * root1[k * HDIM + o];
#pragma unroll
        for (int d = 16; d; d >>= 1) v += __shfl_xor_sync(0xffffffffu, v, d);
        __shared__ float s[8];
        int w = tid >> 5;
        if ((tid & 31) == 0) s[w] = v;
        __syncthreads();
        if (k == 0) g_uroot[o] = s[half * 4] + s[half * 4 + 1] + s[half * 4 + 2] + s[half * 4 + 3];
    }
}

// ---------------- counting / CSR build ---------------------------------------
__global__ void count_k(const int* __restrict__ er, const int* __restrict__ ea,
                        const int* __restrict__ et, int E) {
    int e = blockIdx.x * blockDim.x + threadIdx.x;
    if (e >= E) return;
    atomicAdd(&g_cnt1[ea[e] * RREL + et[e]], 1);
    atomicAdd(&g_cnt2[er[e] * RREL + et[e]], 1);
}

__global__ void scan_blk_all_k() {
    __shared__ int s[1024];
    int t = threadIdx.x;
    bool first = blockIdx.x < NB1;
    int blk = first ? blockIdx.x : blockIdx.x - NB1;
    const int* cnt = first ? g_cnt1 : g_cnt2;
    int* off = first ? g_off1 : g_off2;
    int* bsum = first ? g_bsum1 : g_bsum2;
    int n = first ? B1 : B2;
    int i = blk * 1024 + t;
    int v = (i < n) ? cnt[i] : 0;
    s[t] = v;
    __syncthreads();
#pragma unroll
    for (int d = 1; d < 1024; d <<= 1) {
        int u = (t >= d) ? s[t - d] : 0;
        __syncthreads();
        s[t] += u;
        __syncthreads();
    }
    if (i < n) off[i] = s[t] - v;
    if (t == 1023) bsum[blk] = s[1023];
}

__global__ void scan_top_all_k() {
    __shared__ int s[1024];
    int t = threadIdx.x;
    int* bsum = (blockIdx.x == 0) ? g_bsum1 : g_bsum2;
    int n = (blockIdx.x == 0) ? NB1 : NB2;
    int v = (t < n) ? bsum[t] : 0;
    s[t] = v;
    __syncthreads();
#pragma unroll
    for (int d = 1; d < 1024; d <<= 1) {
        int u = (t >= d) ? s[t - d] : 0;
        __syncthreads();
        s[t] += u;
        __syncthreads();
    }
    if (t < n) bsum[t] = s[t] - v;
}

__global__ void scan_add_all_k() {
    int i = blockIdx.x * blockDim.x + threadIdx.x;
    if (i < B1) {
        int o = g_off1[i] + g_bsum1[i >> 10];
        g_off1[i] = o;
        g_cur1[i] = o;
    } else if (i < B1 + B2) {
        int j = i - B1;
        int o = g_off2[j] + g_bsum2[j >> 10];
        g_off2[j] = o;
        g_cur2[j] = o;
    }
}

__global__ void place_k(const int* __restrict__ er, const int* __restrict__ ea,
                        const int* __restrict__ et, int E) {
    int e = blockIdx.x * blockDim.x + threadIdx.x;
    if (e >= E) return;
    int repo = er[e], actor = ea[e], t = et[e];
    int p1 = atomicAdd(&g_cur1[actor * RREL + t], 1);
    g_perm1[p1] = repo * RREL + t;
    int p2 = atomicAdd(&g_cur2[repo * RREL + t], 1);
    g_perm2[p2] = actor;
}

// ---------------- layer-1 aggregation ----------------------------------------
// HALF-WARP per actor; lane16 covers 16B (8 halfs) of the 256B row.
__global__ void agg1_k(const float* __restrict__ b1, int E) {
    int hw = (blockIdx.x * blockDim.x + threadIdx.x) >> 4;   // actor
    int lane = threadIdx.x & 31;
    int lane16 = lane & 15;
    unsigned seg = 0xFFFFu << (lane & 16);
    if (hw >= NUSER) return;
    float invreg = 0.f;
    if (lane16 < RREL) {
        int d = g_cnt1[hw * RREL + lane16];
        invreg = d ? 1.0f / (float)d : 0.f;
    }
    int start = g_off1[hw * RREL];
    int end = (hw * RREL + RREL < B1) ? g_off1[hw * RREL + RREL] : E;

    float a0, a1, a2, a3, a4, a5, a6, a7;
    {
        float4 ua = *(const float4*)(g_uroot + lane16 * 8);
        float4 ub = *(const float4*)(g_uroot + lane16 * 8 + 4);
        a0 = ua.x; a1 = ua.y; a2 = ua.z; a3 = ua.w;
        a4 = ub.x; a5 = ub.y; a6 = ub.z; a7 = ub.w;
    }

#define ACC1(u, iv) { \
        float2 f0 = __half22float2(((const __half2*)&(u))[0]); \
        float2 f1 = __half22float2(((const __half2*)&(u))[1]); \
        float2 f2 = __half22float2(((const __half2*)&(u))[2]); \
        float2 f3 = __half22float2(((const __half2*)&(u))[3]); \
        a0 = fmaf(f0.x, (iv), a0); a1 = fmaf(f0.y, (iv), a1); \
        a2 = fmaf(f1.x, (iv), a2); a3 = fmaf(f1.y, (iv), a3); \
        a4 = fmaf(f2.x, (iv), a4); a5 = fmaf(f2.y, (iv), a5); \
        a6 = fmaf(f3.x, (iv), a6); a7 = fmaf(f3.y, (iv), a7); }

    int j = start;
    for (; j + 4 <= end; j += 4) {
        int p0 = __ldg(g_perm1 + j),     p1 = __ldg(g_perm1 + j + 1);
        int p2 = __ldg(g_perm1 + j + 2), p3 = __ldg(g_perm1 + j + 3);
        uint4 u0 = *(const uint4*)(g_y1h + (((size_t)p0) << 7) + lane16 * 8);
        uint4 u1 = *(const uint4*)(g_y1h + (((size_t)p1) << 7) + lane16 * 8);
        uint4 u2 = *(const uint4*)(g_y1h + (((size_t)p2) << 7) + lane16 * 8);
        uint4 u3 = *(const uint4*)(g_y1h + (((size_t)p3) << 7) + lane16 * 8);
        float iv0 = __shfl_sync(seg, invreg, (p0 & 7) | (lane & 16));
        float iv1 = __shfl_sync(seg, invreg, (p1 & 7) | (lane & 16));
        float iv2 = __shfl_sync(seg, invreg, (p2 & 7) | (lane & 16));
        float iv3 = __shfl_sync(seg, invreg, (p3 & 7) | (lane & 16));
        ACC1(u0, iv0) ACC1(u1, iv1) ACC1(u2, iv2) ACC1(u3, iv3)
    }
    for (; j < end; j++) {
        int p0 = __ldg(g_perm1 + j);
        uint4 u0 = *(const uint4*)(g_y1h + (((size_t)p0) << 7) + lane16 * 8);
        float iv0 = __shfl_sync(seg, invreg, (p0 & 7) | (lane & 16));
        ACC1(u0, iv0)
    }
#undef ACC1

    float4 ba = *(const float4*)(b1 + lane16 * 8);
    float4 bb = *(const float4*)(b1 + lane16 * 8 + 4);
    uint4 pk;
    __half2 h0 = __floats2half2_rn(fmaxf(a0 + ba.x, 0.f), fmaxf(a1 + ba.y, 0.f));
    __half2 h1 = __floats2half2_rn(fmaxf(a2 + ba.z, 0.f), fmaxf(a3 + ba.w, 0.f));
    __half2 h2 = __floats2half2_rn(fmaxf(a4 + bb.x, 0.f), fmaxf(a5 + bb.y, 0.f));
    __half2 h3 = __floats2half2_rn(fmaxf(a6 + bb.z, 0.f), fmaxf(a7 + bb.w, 0.f));
    pk.x = *(unsigned*)&h0; pk.y = *(unsigned*)&h1;
    pk.z = *(unsigned*)&h2; pk.w = *(unsigned*)&h3;
    *(uint4*)(g_h1h + (((size_t)(NREPO + hw)) << 7) + lane16 * 8) = pk;
}

// ================= bf16 3-term tensor-core GEMM pieces =======================
#define PITCH 136
#define AH_OFF 0
#define AL_OFF 34816
#define BH_OFF 69632
#define BL_OFF 104448
#define MMA_SMEM 139264

__device__ __forceinline__ uint32_t smem_u32(const void* p) {
    uint32_t a;
    asm("{ .reg .u64 t; cvta.to.shared.u64 t, %1; cvt.u32.u64 %0, t; }" : "=r"(a) : "l"(p));
    return a;
}

__device__ __forceinline__ void ldsm_x4(unsigned r[4], uint32_t addr) {
    asm volatile("ldmatrix.sync.aligned.m8n8.x4.shared.b16 {%0,%1,%2,%3}, [%4];"
                 : "=r"(r[0]), "=r"(r[1]), "=r"(r[2]), "=r"(r[3]) : "r"(addr));
}

__device__ __forceinline__ void ldsm_x4_t(unsigned r[4], uint32_t addr) {
    asm volatile("ldmatrix.sync.aligned.m8n8.x4.trans.shared.b16 {%0,%1,%2,%3}, [%4];"
                 : "=r"(r[0]), "=r"(r[1]), "=r"(r[2]), "=r"(r[3]) : "r"(addr));
}

__device__ __forceinline__ void mma_bf16(float c[4], const unsigned a[4], const unsigned* b) {
    asm volatile(
        "mma.sync.aligned.m16n8k16.row.col.f32.bf16.bf16.f32 "
        "{%0,%1,%2,%3}, {%4,%5,%6,%7}, {%8,%9}, {%0,%1,%2,%3};"
        : "+f"(c[0]), "+f"(c[1]), "+f"(c[2]), "+f"(c[3])
        : "r"(a[0]), "r"(a[1]), "r"(a[2]), "r"(a[3]), "r"(b[0]), "r"(b[1]));
}

__device__ __forceinline__ void sp_bf(float x, unsigned short& h, unsigned short& l) {
    __nv_bfloat16 hb = __float2bfloat16_rn(x);
    h = __bfloat16_as_ushort(hb);
    l = __bfloat16_as_ushort(__float2bfloat16_rn(x - __bfloat162float(hb)));
}

__device__ __forceinline__ void store_planes(char* sm, int plane_off_h, int plane_off_l,
                                             int row, int c4, float4 f) {
    unsigned short h0, h1, h2, h3, l0, l1, l2, l3;
    sp_bf(f.x, h0, l0); sp_bf(f.y, h1, l1); sp_bf(f.z, h2, l2); sp_bf(f.w, h3, l3);
    int off = (row * PITCH + c4) * 2;
    *(uint2*)(sm + plane_off_h + off) = make_uint2((unsigned)h0 | ((unsigned)h1 << 16),
                                                   (unsigned)h2 | ((unsigned)h3 << 16));
    *(uint2*)(sm + plane_off_l + off) = make_uint2((unsigned)l0 | ((unsigned)l1 << 16),
                                                   (unsigned)l2 | ((unsigned)l3 << 16));
}

__device__ __forceinline__ void load_A_f32(char* sm, const float* __restrict__ A, int lda,
                                           int m0, int M, int tid) {
#pragma unroll
    for (int it = 0; it < 16; it++) {
        int v = tid + it * 256;
        int row = v >> 5;
        int c4 = (v & 31) * 4;
        float4 fa = (m0 + row < M) ? *(const float4*)(A + (size_t)(m0 + row) * lda + c4)
                                   : make_float4(0.f, 0.f, 0.f, 0.f);
        store_planes(sm, AH_OFF, AL_OFF, row, c4, fa);
    }
}

__device__ __forceinline__ void load_A_f16(char* sm, const __half* __restrict__ A, int lda,
                                           int cO, int m0, int M, int tid) {
#pragma unroll
    for (int it = 0; it < 16; it++) {
        int v = tid + it * 256;
        int row = v >> 5;
        int c4 = (v & 31) * 4;
        float4 fa = make_float4(0.f, 0.f, 0.f, 0.f);
        if (m0 + row < M) {
            uint2 u = *(const uint2*)(A + (size_t)(m0 + row) * lda + cO + c4);
            float2 lo = __half22float2(((const __half2*)&u)[0]);
            float2 hi = __half22float2(((const __half2*)&u)[1]);
            fa = make_float4(lo.x, lo.y, hi.x, hi.y);
        }
        store_planes(sm, AH_OFF, AL_OFF, row, c4, fa);
    }
}

__device__ __forceinline__ void load_B_f32(char* sm, const float* __restrict__ B, int tid) {
#pragma unroll
    for (int it = 0; it < 16; it++) {
        int v = tid + it * 256;
        int row = v >> 5;
        int c4 = (v & 31) * 4;
        float4 fb = *(const float4*)(B + (size_t)row * 128 + c4);
        store_planes(sm, BH_OFF, BL_OFF, row, c4, fb);
    }
}

__device__ __forceinline__ void compute_planes(uint32_t sb, int wm, int wn, int lrow,
                                               int lhalf, float (&acc)[4][4][4]) {
#pragma unroll 1
    for (int kc = 0; kc < 8; kc++) {
        int k0 = kc * 16;
        unsigned Ah[4][4], Al[4][4], Bh[2][4], Bl[2][4];
#pragma unroll
        for (int mf = 0; mf < 4; mf++) {
            uint32_t a = sb + ((wm + mf * 16 + lrow) * PITCH + k0 + lhalf) * 2;
            ldsm_x4(Ah[mf], a + AH_OFF);
            ldsm_x4(Al[mf], a + AL_OFF);
        }
#pragma unroll
        for (int np = 0; np < 2; np++) {
            uint32_t a = sb + ((k0 + lrow) * PITCH + wn + np * 16 + lhalf) * 2;
            ldsm_x4_t(Bh[np], a + BH_OFF);
            ldsm_x4_t(Bl[np], a + BL_OFF);
        }
#pragma unroll
        for (int mf = 0; mf < 4; mf++)
#pragma unroll
            for (int nf = 0; nf < 4; nf++) {
                const unsigned* bh = &Bh[nf >> 1][(nf & 1) * 2];
                const unsigned* bl = &Bl[nf >> 1][(nf & 1) * 2];
                mma_bf16(acc[mf][nf], Ah[mf], bh);
                mma_bf16(acc[mf][nf], Al[mf], bh);
                mma_bf16(acc[mf][nf], Ah[mf], bl);
            }
    }
}

// y1 + root1 fused
__global__ void __launch_bounds__(256)
y1root_k(const float* __restrict__ A, int M, const float* __restrict__ w1,
         const float* __restrict__ root1, const float* __restrict__ bias) {
    extern __shared__ char sm[];
    const uint32_t sb = smem_u32(sm);
    const int tid = threadIdx.x;
    const int lane = tid & 31;
    const int warp = tid >> 5;
    const int wm = (warp >> 2) * 64;
    const int wn = (warp & 3) * 32;
    const int m0 = blockIdx.x * 128;
    const int lrow = lane & 15;
    const int lhalf = (lane >> 4) * 8;
    const int z = blockIdx.z;
    const int nmat = (z == 4) ? 1 : 2;

    load_A_f32(sm, A, HDIM, m0, M, tid);

#pragma unroll 1
    for (int rr = 0; rr < nmat; rr++) {
        const float* B = (z == 4) ? root1 : (w1 + (size_t)(z * 2 + rr) * HDIM * HDIM);
        load_B_f32(sm, B, tid);
        __syncthreads();

        float acc[4][4][4];
#pragma unroll
        for (int i = 0; i < 4; i++)
#pragma unroll
            for (int j = 0; j < 4; j++)
#pragma unroll
                for (int k = 0; k < 4; k++) acc[i][j][k] = 0.f;

        compute_planes(sb, wm, wn, lrow, lhalf, acc);

#pragma unroll
        for (int mf = 0; mf < 4; mf++)
#pragma unroll
            for (int nf = 0; nf < 4; nf++) {
                int r0 = m0 + wm + mf * 16 + (lane >> 2);
                int r1 = r0 + 8;
                int cl = wn + nf * 8 + (lane & 3) * 2;
                if (z == 4) {
                    float b0 = bias[cl], b1v = bias[cl + 1];
                    if (r0 < M)
                        *(__half2*)(g_h1h + (size_t)r0 * HDIM + cl) =
                            __floats2half2_rn(fmaxf(acc[mf][nf][0] + b0, 0.f),
                                              fmaxf(acc[mf][nf][1] + b1v, 0.f));
                    if (r1 < M)
                        *(__half2*)(g_h1h + (size_t)r1 * HDIM + cl) =
                            __floats2half2_rn(fmaxf(acc[mf][nf][2] + b0, 0.f),
                                              fmaxf(acc[mf][nf][3] + b1v, 0.f));
                } else {
                    int r = z * 2 + rr;
                    if (r0 < M)
                        *(__half2*)(g_y1h + (size_t)r0 * (RREL * HDIM) + r * HDIM + cl) =
                            __floats2half2_rn(acc[mf][nf][0], acc[mf][nf][1]);
                    if (r1 < M)
                        *(__half2*)(g_y1h + (size_t)r1 * (RREL * HDIM) + r * HDIM + cl) =
                            __floats2half2_rn(acc[mf][nf][2], acc[mf][nf][3]);
                }
            }
        __syncthreads();
    }
}

// fused layer-2 + in-kernel aggregation + classifier.
// slab s<8: A rows = mean over edges of h1h[actor] for bin (repo, s), computed
// on the fly (no sum2 buffer).  slab s==8: A = h1h[repo] (root term).
__global__ void __launch_bounds__(256)
l2_k(const __half* __restrict__ h1,
     const float* __restrict__ w2, const float* __restrict__ root2,
     const float* __restrict__ b2, const float* __restrict__ clsw,
     const float* __restrict__ clsb, float* __restrict__ out, int M) {
    extern __shared__ char sm[];
    const uint32_t sb = smem_u32(sm);
    const int tid = threadIdx.x;
    const int lane = tid & 31;
    const int warp = tid >> 5;
    const int wm = (warp >> 2) * 64;
    const int wn = (warp & 3) * 32;
    const int m0 = blockIdx.x * 128;
    const int lrow = lane & 15;
    const int lhalf = (lane >> 4) * 8;
    const int lane16 = tid & 15;

    float acc[4][4][4];
#pragma unroll
    for (int i = 0; i < 4; i++)
#pragma unroll
        for (int j = 0; j < 4; j++)
#pragma unroll
            for (int k = 0; k < 4; k++) acc[i][j][k] = 0.f;

#pragma unroll 1
    for (int s = 0; s < 9; s++) {
        if (s < 8) {
            // gather+mean directly into A planes: half-warp per output row
#pragma unroll 1
            for (int it = 0; it < 8; it++) {
                int row = it * 16 + (tid >> 4);     // 0..127
                float a0 = 0.f, a1 = 0.f, a2 = 0.f, a3 = 0.f,
                      a4 = 0.f, a5 = 0.f, a6 = 0.f, a7 = 0.f;
                int deg = 0;
                int repo = m0 + row;
                if (repo < M) {
                    int bin = repo * RREL + s;
                    deg = g_cnt2[bin];
                    int start = g_off2[bin];
#define ACC2(u) { \
        float2 f0 = __half22float2(((const __half2*)&(u))[0]); \
        float2 f1 = __half22float2(((const __half2*)&(u))[1]); \
        float2 f2 = __half22float2(((const __half2*)&(u))[2]); \
        float2 f3 = __half22float2(((const __half2*)&(u))[3]); \
        a0 += f0.x; a1 += f0.y; a2 += f1.x; a3 += f1.y; \
        a4 += f2.x; a5 += f2.y; a6 += f3.x; a7 += f3.y; }
                    int j = 0;
                    for (; j + 4 <= deg; j += 4) {
                        int c0 = __ldg(g_perm2 + start + j);
                        int c1 = __ldg(g_perm2 + start + j + 1);
                        int c2 = __ldg(g_perm2 + start + j + 2);
                        int c3 = __ldg(g_perm2 + start + j + 3);
                        uint4 u0 = *(const uint4*)(h1 + (((size_t)(NREPO + c0)) << 7) + lane16 * 8);
                        uint4 u1 = *(const uint4*)(h1 + (((size_t)(NREPO + c1)) << 7) + lane16 * 8);
                        uint4 u2 = *(const uint4*)(h1 + (((size_t)(NREPO + c2)) << 7) + lane16 * 8);
                        uint4 u3 = *(const uint4*)(h1 + (((size_t)(NREPO + c3)) << 7) + lane16 * 8);
                        ACC2(u0) ACC2(u1) ACC2(u2) ACC2(u3)
                    }
                    for (; j < deg; j++) {
                        int c0 = __ldg(g_perm2 + start + j);
                        uint4 u0 = *(const uint4*)(h1 + (((size_t)(NREPO + c0)) << 7) + lane16 * 8);
                        ACC2(u0)
                    }
#undef ACC2
                }
                float inv = deg ? 1.0f / (float)deg : 0.f;
                store_planes(sm, AH_OFF, AL_OFF, row, lane16 * 8,
                             make_float4(a0 * inv, a1 * inv, a2 * inv, a3 * inv));
                store_planes(sm, AH_OFF, AL_OFF, row, lane16 * 8 + 4,
                             make_float4(a4 * inv, a5 * inv, a6 * inv, a7 * inv));
            }
        } else {
            load_A_f16(sm, h1, HDIM, 0, m0, M, tid);
        }
        load_B_f32(sm, (s < 8) ? (w2 + (size_t)s * HDIM * HDIM) : root2, tid);
        __syncthreads();
        compute_planes(sb, wm, wn, lrow, lhalf, acc);
        __syncthreads();
    }

    float* redA = (float*)sm;
    float* redB = (float*)sm + 512;
#pragma unroll
    for (int mf = 0; mf < 4; mf++) {
        float p0a = 0.f, p0b = 0.f, p1a = 0.f, p1b = 0.f;
#pragma unroll
        for (int nf = 0; nf < 4; nf++) {
            int cl = wn + nf * 8 + (lane & 3) * 2;
            float b0 = b2[cl], b1v = b2[cl + 1];
            float w00 = clsw[cl * 2], w01 = clsw[cl * 2 + 1];
            float w10 = clsw[(cl + 1) * 2], w11 = clsw[(cl + 1) * 2 + 1];
            float v0 = fmaxf(acc[mf][nf][0] + b0, 0.f);
            float v1 = fmaxf(acc[mf][nf][1] + b1v, 0.f);
            float v2 = fmaxf(acc[mf][nf][2] + b0, 0.f);
            float v3 = fmaxf(acc[mf][nf][3] + b1v, 0.f);
            p0a += v0 * w00 + v1 * w10; p0b += v0 * w01 + v1 * w11;
            p1a += v2 * w00 + v3 * w10; p1b += v2 * w01 + v3 * w11;
        }
#pragma unroll
        for (int o = 1; o <= 2; o <<= 1) {
            p0a += __shfl_xor_sync(0xffffffffu, p0a, o);
            p0b += __shfl_xor_sync(0xffffffffu, p0b, o);
            p1a += __shfl_xor_sync(0xffffffffu, p1a, o);
            p1b += __shfl_xor_sync(0xffffffffu, p1b, o);
        }
        if ((lane & 3) == 0) {
            int r0 = wm + mf * 16 + (lane >> 2);
            redA[r0 * 4 + (warp & 3)] = p0a;
            redB[r0 * 4 + (warp & 3)] = p0b;
            redA[(r0 + 8) * 4 + (warp & 3)] = p1a;
            redB[(r0 + 8) * 4 + (warp & 3)] = p1b;
        }
    }
    __syncthreads();
    if (tid < 128) {
        int gr = m0 + tid;
        if (gr < M) {
            float o0 = redA[tid * 4] + redA[tid * 4 + 1] + redA[tid * 4 + 2] + redA[tid * 4 + 3] + clsb[0];
            float o1 = redB[tid * 4] + redB[tid * 4 + 1] + redB[tid * 4 + 2] + redB[tid * 4 + 3] + clsb[1];
            out[gr * 2 + 0] = o0;
            out[gr * 2 + 1] = o1;
        }
    }
}

// ---------------- driver (single stream) -------------------------------------
extern "C" void kernel_launch(void* const* d_in, const int* in_sizes, int n_in,
                              void* d_out, int out_size) {
    const float* x     = (const float*)d_in[0];
    const int*   er    = (const int*)d_in[1];
    const int*   ea    = (const int*)d_in[2];
    const int*   et    = (const int*)d_in[3];
    const float* mlp_w = (const float*)d_in[4];
    const float* mlp_b = (const float*)d_in[5];
    const float* w1    = (const float*)d_in[6];
    const float* root1 = (const float*)d_in[7];
    const float* b1    = (const float*)d_in[8];
    const float* w2    = (const float*)d_in[9];
    const float* root2 = (const float*)d_in[10];
    const float* b2    = (const float*)d_in[11];
    const float* cls_w = (const float*)d_in[12];
    const float* cls_b = (const float*)d_in[13];
    int E = in_sizes[1];
    float* out = (float*)d_out;

    void *pH0, *pH1h;
    cudaGetSymbolAddress(&pH0, g_h0);
    cudaGetSymbolAddress(&pH1h, g_h1h);

    cudaFuncSetAttribute(y1root_k, cudaFuncAttributeMaxDynamicSharedMemorySize, MMA_SMEM);
    cudaFuncSetAttribute(l2_k, cudaFuncAttributeMaxDynamicSharedMemorySize, MMA_SMEM);

    const int GB = (NREPO + 127) / 128;   // 235

    // K1: zero counters | mlp | uroot
    front_k<<<ZBLKS + MBLKS + UBLKS, 256>>>(x, mlp_w, mlp_b, root1);
    // K2-K6: CSR construction
    count_k<<<(E + 255) / 256, 256>>>(er, ea, et, E);
    scan_blk_all_k<<<NB1 + NB2, 1024>>>();
    scan_top_all_k<<<2, 1024>>>();
    scan_add_all_k<<<(B1 + B2 + 255) / 256, 256>>>();
    place_k<<<(E + 255) / 256, 256>>>(er, ea, et, E);
    // K7: y1 (8 relations) + root1
    y1root_k<<<dim3(GB, 1, 5), 256, MMA_SMEM>>>((const float*)pH0, NREPO, w1, root1, b1);
    // K8: layer-1 aggregation
    agg1_k<<<(NUSER * 16 + 255) / 256, 256>>>(b1, E);
    // K9: fused layer-2 (in-kernel aggregation + GEMM + classifier)
    l2_k<<<GB, 256, MMA_SMEM>>>(
        (const __half*)pH1h, w2, root2, b2, cls_w, cls_b, out, NREPO);
}

// round 13
// speedup vs baseline: 1.2454x; 1.2454x over previous
#include <cuda_runtime.h>
#include <cuda_bf16.h>
#include <cuda_fp16.h>
#include <cstdint>

#define NREPO 30000
#define NUSER 70000
#define NNODE 100000
#define RREL  8
#define HDIM  128
#define B1 (NUSER * RREL)
#define B2 (NREPO * RREL)
#define NB1 ((B1 + 1023) / 1024)
#define NB2 ((B2 + 1023) / 1024)
#define EMAX 1000000

// fused front kernel block ranges
#define ZBLKS ((B1 + 255) / 256)
#define MBLKS ((NREPO * HDIM + 255) / 256)
#define UBLKS (HDIM / 2)

// ---------------- scratch ----------------------------------------------------
__device__ float  g_h0[(size_t)NREPO * HDIM];
__device__ __half g_h1h[(size_t)NNODE * HDIM];
__device__ __half g_y1h[(size_t)B2 * HDIM];
__device__ __half g_sum2h[(size_t)B2 * HDIM];
__device__ float  g_uroot[HDIM];
__device__ int    g_cnt1[B1], g_off1[B1], g_cur1[B1], g_bsum1[NB1];
__device__ int    g_cnt2[B2], g_off2[B2], g_cur2[B2], g_bsum2[NB2];
__device__ int    g_perm1[EMAX];
__device__ int    g_perm2[EMAX];

// ---------------- fused front: zero counters | mlp | uroot -------------------
__global__ void front_k(const float* __restrict__ x, const float* __restrict__ mlp_w,
                        const float* __restrict__ mlp_b, const float* __restrict__ root1) {
    int bx = blockIdx.x;
    int tid = threadIdx.x;
    if (bx < ZBLKS) {
        int i = bx * 256 + tid;
        if (i < B1) g_cnt1[i] = 0;
        if (i < B2) g_cnt2[i] = 0;
        return;
    }
    bx -= ZBLKS;
    if (bx < MBLKS) {
        int g = bx * 256 + tid;
        if (g >= NREPO * HDIM) return;
        int n = g >> 7, o = g & 127;
        float acc = mlp_b[o];
#pragma unroll
        for (int k = 0; k < 8; k++)
            acc = fmaf(__ldg(&x[n * 8 + k]), __ldg(&mlp_w[k * HDIM + o]), acc);
        g_h0[g] = fmaxf(acc, 0.f);
        return;
    }
    bx -= MBLKS;
    {
        int half = tid >> 7;
        int k = tid & 127;
        int o = bx * 2 + half;
        float v = fmaxf(mlp_b[k], 0.f) * root1[k * HDIM + o];
#pragma unroll
        for (int d = 16; d; d >>= 1) v += __shfl_xor_sync(0xffffffffu, v, d);
        __shared__ float s[8];
        int w = tid >> 5;
        if ((tid & 31) == 0) s[w] = v;
        __syncthreads();
        if (k == 0) g_uroot[o] = s[half * 4] + s[half * 4 + 1] + s[half * 4 + 2] + s[half * 4 + 3];
    }
}

// ---------------- counting / CSR build ---------------------------------------
__global__ void count_k(const int* __restrict__ er, const int* __restrict__ ea,
                        const int* __restrict__ et, int E) {
    int e = blockIdx.x * blockDim.x + threadIdx.x;
    if (e >= E) return;
    atomicAdd(&g_cnt1[ea[e] * RREL + et[e]], 1);
    atomicAdd(&g_cnt2[er[e] * RREL + et[e]], 1);
}

__global__ void scan_blk_all_k() {
    __shared__ int s[1024];
    int t = threadIdx.x;
    bool first = blockIdx.x < NB1;
    int blk = first ? blockIdx.x : blockIdx.x - NB1;
    const int* cnt = first ? g_cnt1 : g_cnt2;
    int* off = first ? g_off1 : g_off2;
    int* bsum = first ? g_bsum1 : g_bsum2;
    int n = first ? B1 : B2;
    int i = blk * 1024 + t;
    int v = (i < n) ? cnt[i] : 0;
    s[t] = v;
    __syncthreads();
#pragma unroll
    for (int d = 1; d < 1024; d <<= 1) {
        int u = (t >= d) ? s[t - d] : 0;
        __syncthreads();
        s[t] += u;
        __syncthreads();
    }
    if (i < n) off[i] = s[t] - v;
    if (t == 1023) bsum[blk] = s[1023];
}

// scan_add with inlined top-level prefix: each block reduces bsum[0..blk)
__global__ void scan_add_all_k() {
    int t = threadIdx.x;                       // 1024 threads
    bool first = blockIdx.x < NB1;
    int blk = first ? blockIdx.x : blockIdx.x - NB1;
    const int* bsum = first ? g_bsum1 : g_bsum2;

    int partial = 0;
    for (int i = t; i < blk; i += 1024) partial += bsum[i];
#pragma unroll
    for (int d = 16; d; d >>= 1) partial += __shfl_xor_sync(0xffffffffu, partial, d);
    __shared__ int red[32];
    if ((t & 31) == 0) red[t >> 5] = partial;
    __syncthreads();
    __shared__ int base;
    if (t == 0) {
        int b = 0;
#pragma unroll
        for (int w = 0; w < 32; w++) b += red[w];
        base = b;
    }
    __syncthreads();
    int bs = base;

    int i = blk * 1024 + t;
    if (first) {
        if (i < B1) {
            int o = g_off1[i] + bs;
            g_off1[i] = o;
            g_cur1[i] = o;
        }
    } else {
        if (i < B2) {
            int o = g_off2[i] + bs;
            g_off2[i] = o;
            g_cur2[i] = o;
        }
    }
}

__global__ void place_k(const int* __restrict__ er, const int* __restrict__ ea,
                        const int* __restrict__ et, int E) {
    int e = blockIdx.x * blockDim.x + threadIdx.x;
    if (e >= E) return;
    int repo = er[e], actor = ea[e], t = et[e];
    int p1 = atomicAdd(&g_cur1[actor * RREL + t], 1);
    g_perm1[p1] = repo * RREL + t;
    int p2 = atomicAdd(&g_cur2[repo * RREL + t], 1);
    g_perm2[p2] = actor;
}

// ---------------- aggregations ------------------------------------------------
// layer-1: HALF-WARP per actor; lane16 covers 16B (8 halfs) of the 256B row.
__global__ void agg1_k(const float* __restrict__ b1, int E) {
    int hw = (blockIdx.x * blockDim.x + threadIdx.x) >> 4;   // actor
    int lane = threadIdx.x & 31;
    int lane16 = lane & 15;
    unsigned seg = 0xFFFFu << (lane & 16);
    if (hw >= NUSER) return;
    float invreg = 0.f;
    if (lane16 < RREL) {
        int d = g_cnt1[hw * RREL + lane16];
        invreg = d ? 1.0f / (float)d : 0.f;
    }
    int start = g_off1[hw * RREL];
    int end = (hw * RREL + RREL < B1) ? g_off1[hw * RREL + RREL] : E;

    float a0, a1, a2, a3, a4, a5, a6, a7;
    {
        float4 ua = *(const float4*)(g_uroot + lane16 * 8);
        float4 ub = *(const float4*)(g_uroot + lane16 * 8 + 4);
        a0 = ua.x; a1 = ua.y; a2 = ua.z; a3 = ua.w;
        a4 = ub.x; a5 = ub.y; a6 = ub.z; a7 = ub.w;
    }

#define ACC1(u, iv) { \
        float2 f0 = __half22float2(((const __half2*)&(u))[0]); \
        float2 f1 = __half22float2(((const __half2*)&(u))[1]); \
        float2 f2 = __half22float2(((const __half2*)&(u))[2]); \
        float2 f3 = __half22float2(((const __half2*)&(u))[3]); \
        a0 = fmaf(f0.x, (iv), a0); a1 = fmaf(f0.y, (iv), a1); \
        a2 = fmaf(f1.x, (iv), a2); a3 = fmaf(f1.y, (iv), a3); \
        a4 = fmaf(f2.x, (iv), a4); a5 = fmaf(f2.y, (iv), a5); \
        a6 = fmaf(f3.x, (iv), a6); a7 = fmaf(f3.y, (iv), a7); }

    int j = start;
    for (; j + 4 <= end; j += 4) {
        int p0 = __ldg(g_perm1 + j),     p1 = __ldg(g_perm1 + j + 1);
        int p2 = __ldg(g_perm1 + j + 2), p3 = __ldg(g_perm1 + j + 3);
        uint4 u0 = *(const uint4*)(g_y1h + (((size_t)p0) << 7) + lane16 * 8);
        uint4 u1 = *(const uint4*)(g_y1h + (((size_t)p1) << 7) + lane16 * 8);
        uint4 u2 = *(const uint4*)(g_y1h + (((size_t)p2) << 7) + lane16 * 8);
        uint4 u3 = *(const uint4*)(g_y1h + (((size_t)p3) << 7) + lane16 * 8);
        float iv0 = __shfl_sync(seg, invreg, (p0 & 7) | (lane & 16));
        float iv1 = __shfl_sync(seg, invreg, (p1 & 7) | (lane & 16));
        float iv2 = __shfl_sync(seg, invreg, (p2 & 7) | (lane & 16));
        float iv3 = __shfl_sync(seg, invreg, (p3 & 7) | (lane & 16));
        ACC1(u0, iv0) ACC1(u1, iv1) ACC1(u2, iv2) ACC1(u3, iv3)
    }
    for (; j < end; j++) {
        int p0 = __ldg(g_perm1 + j);
        uint4 u0 = *(const uint4*)(g_y1h + (((size_t)p0) << 7) + lane16 * 8);
        float iv0 = __shfl_sync(seg, invreg, (p0 & 7) | (lane & 16));
        ACC1(u0, iv0)
    }
#undef ACC1

    float4 ba = *(const float4*)(b1 + lane16 * 8);
    float4 bb = *(const float4*)(b1 + lane16 * 8 + 4);
    uint4 pk;
    __half2 h0 = __floats2half2_rn(fmaxf(a0 + ba.x, 0.f), fmaxf(a1 + ba.y, 0.f));
    __half2 h1 = __floats2half2_rn(fmaxf(a2 + ba.z, 0.f), fmaxf(a3 + ba.w, 0.f));
    __half2 h2 = __floats2half2_rn(fmaxf(a4 + bb.x, 0.f), fmaxf(a5 + bb.y, 0.f));
    __half2 h3 = __floats2half2_rn(fmaxf(a6 + bb.z, 0.f), fmaxf(a7 + bb.w, 0.f));
    pk.x = *(unsigned*)&h0; pk.y = *(unsigned*)&h1;
    pk.z = *(unsigned*)&h2; pk.w = *(unsigned*)&h3;
    *(uint4*)(g_h1h + (((size_t)(NREPO + hw)) << 7) + lane16 * 8) = pk;
}

// layer-2: HALF-WARP per (repo, relation) bin, uint4 loads, 4-way unroll
__global__ void agg2_k() {
    int bin = (blockIdx.x * blockDim.x + threadIdx.x) >> 4;
    int lane16 = threadIdx.x & 15;
    if (bin >= B2) return;
    int deg = g_cnt2[bin];
    int start = g_off2[bin];
    float a0 = 0.f, a1 = 0.f, a2 = 0.f, a3 = 0.f, a4 = 0.f, a5 = 0.f, a6 = 0.f, a7 = 0.f;
#define ACC2(u) { \
        float2 f0 = __half22float2(((const __half2*)&(u))[0]); \
        float2 f1 = __half22float2(((const __half2*)&(u))[1]); \
        float2 f2 = __half22float2(((const __half2*)&(u))[2]); \
        float2 f3 = __half22float2(((const __half2*)&(u))[3]); \
        a0 += f0.x; a1 += f0.y; a2 += f1.x; a3 += f1.y; \
        a4 += f2.x; a5 += f2.y; a6 += f3.x; a7 += f3.y; }
    int j = 0;
    for (; j + 4 <= deg; j += 4) {
        int c0 = __ldg(g_perm2 + start + j);
        int c1 = __ldg(g_perm2 + start + j + 1);
        int c2 = __ldg(g_perm2 + start + j + 2);
        int c3 = __ldg(g_perm2 + start + j + 3);
        uint4 u0 = *(const uint4*)(g_h1h + (((size_t)(NREPO + c0)) << 7) + lane16 * 8);
        uint4 u1 = *(const uint4*)(g_h1h + (((size_t)(NREPO + c1)) << 7) + lane16 * 8);
        uint4 u2 = *(const uint4*)(g_h1h + (((size_t)(NREPO + c2)) << 7) + lane16 * 8);
        uint4 u3 = *(const uint4*)(g_h1h + (((size_t)(NREPO + c3)) << 7) + lane16 * 8);
        ACC2(u0) ACC2(u1) ACC2(u2) ACC2(u3)
    }
    for (; j < deg; j++) {
        int c0 = __ldg(g_perm2 + start + j);
        uint4 u0 = *(const uint4*)(g_h1h + (((size_t)(NREPO + c0)) << 7) + lane16 * 8);
        ACC2(u0)
    }
#undef ACC2
    float inv = deg ? 1.0f / (float)deg : 0.f;
    uint4 pk;
    __half2 h0 = __floats2half2_rn(a0 * inv, a1 * inv);
    __half2 h1 = __floats2half2_rn(a2 * inv, a3 * inv);
    __half2 h2 = __floats2half2_rn(a4 * inv, a5 * inv);
    __half2 h3 = __floats2half2_rn(a6 * inv, a7 * inv);
    pk.x = *(unsigned*)&h0; pk.y = *(unsigned*)&h1;
    pk.z = *(unsigned*)&h2; pk.w = *(unsigned*)&h3;
    *(uint4*)(g_sum2h + ((size_t)bin << 7) + lane16 * 8) = pk;
}

// ================= bf16 3-term tensor-core GEMM pieces =======================
#define PITCH 136
#define AH_OFF 0
#define AL_OFF 34816
#define BH_OFF 69632
#define BL_OFF 104448
#define MMA_SMEM 139264

__device__ __forceinline__ uint32_t smem_u32(const void* p) {
    uint32_t a;
    asm("{ .reg .u64 t; cvta.to.shared.u64 t, %1; cvt.u32.u64 %0, t; }" : "=r"(a) : "l"(p));
    return a;
}

__device__ __forceinline__ void ldsm_x4(unsigned r[4], uint32_t addr) {
    asm volatile("ldmatrix.sync.aligned.m8n8.x4.shared.b16 {%0,%1,%2,%3}, [%4];"
                 : "=r"(r[0]), "=r"(r[1]), "=r"(r[2]), "=r"(r[3]) : "r"(addr));
}

__device__ __forceinline__ void ldsm_x4_t(unsigned r[4], uint32_t addr) {
    asm volatile("ldmatrix.sync.aligned.m8n8.x4.trans.shared.b16 {%0,%1,%2,%3}, [%4];"
                 : "=r"(r[0]), "=r"(r[1]), "=r"(r[2]), "=r"(r[3]) : "r"(addr));
}

__device__ __forceinline__ void mma_bf16(float c[4], const unsigned a[4], const unsigned* b) {
    asm volatile(
        "mma.sync.aligned.m16n8k16.row.col.f32.bf16.bf16.f32 "
        "{%0,%1,%2,%3}, {%4,%5,%6,%7}, {%8,%9}, {%0,%1,%2,%3};"
        : "+f"(c[0]), "+f"(c[1]), "+f"(c[2]), "+f"(c[3])
        : "r"(a[0]), "r"(a[1]), "r"(a[2]), "r"(a[3]), "r"(b[0]), "r"(b[1]));
}

__device__ __forceinline__ void sp_bf(float x, unsigned short& h, unsigned short& l) {
    __nv_bfloat16 hb = __float2bfloat16_rn(x);
    h = __bfloat16_as_ushort(hb);
    l = __bfloat16_as_ushort(__float2bfloat16_rn(x - __bfloat162float(hb)));
}

__device__ __forceinline__ void store_planes(char* sm, int plane_off_h, int plane_off_l,
                                             int row, int c4, float4 f) {
    unsigned short h0, h1, h2, h3, l0, l1, l2, l3;
    sp_bf(f.x, h0, l0); sp_bf(f.y, h1, l1); sp_bf(f.z, h2, l2); sp_bf(f.w, h3, l3);
    int off = (row * PITCH + c4) * 2;
    *(uint2*)(sm + plane_off_h + off) = make_uint2((unsigned)h0 | ((unsigned)h1 << 16),
                                                   (unsigned)h2 | ((unsigned)h3 << 16));
    *(uint2*)(sm + plane_off_l + off) = make_uint2((unsigned)l0 | ((unsigned)l1 << 16),
                                                   (unsigned)l2 | ((unsigned)l3 << 16));
}

__device__ __forceinline__ void load_A_f32(char* sm, const float* __restrict__ A, int lda,
                                           int m0, int M, int tid) {
#pragma unroll
    for (int it = 0; it < 16; it++) {
        int v = tid + it * 256;
        int row = v >> 5;
        int c4 = (v & 31) * 4;
        float4 fa = (m0 + row < M) ? *(const float4*)(A + (size_t)(m0 + row) * lda + c4)
                                   : make_float4(0.f, 0.f, 0.f, 0.f);
        store_planes(sm, AH_OFF, AL_OFF, row, c4, fa);
    }
}

__device__ __forceinline__ void load_A_f16(char* sm, const __half* __restrict__ A, int lda,
                                           int cO, int m0, int M, int tid) {
#pragma unroll
    for (int it = 0; it < 16; it++) {
        int v = tid + it * 256;
        int row = v >> 5;
        int c4 = (v & 31) * 4;
        float4 fa = make_float4(0.f, 0.f, 0.f, 0.f);
        if (m0 + row < M) {
            uint2 u = *(const uint2*)(A + (size_t)(m0 + row) * lda + cO + c4);
            float2 lo = __half22float2(((const __half2*)&u)[0]);
            float2 hi = __half22float2(((const __half2*)&u)[1]);
            fa = make_float4(lo.x, lo.y, hi.x, hi.y);
        }
        store_planes(sm, AH_OFF, AL_OFF, row, c4, fa);
    }
}

__device__ __forceinline__ void load_B_f32(char* sm, const float* __restrict__ B, int tid) {
#pragma unroll
    for (int it = 0; it < 16; it++) {
        int v = tid + it * 256;
        int row = v >> 5;
        int c4 = (v & 31) * 4;
        float4 fb = *(const float4*)(B + (size_t)row * 128 + c4);
        store_planes(sm, BH_OFF, BL_OFF, row, c4, fb);
    }
}

__device__ __forceinline__ void compute_planes(uint32_t sb, int wm, int wn, int lrow,
                                               int lhalf, float (&acc)[4][4][4]) {
#pragma unroll 1
    for (int kc = 0; kc < 8; kc++) {
        int k0 = kc * 16;
        unsigned Ah[4][4], Al[4][4], Bh[2][4], Bl[2][4];
#pragma unroll
        for (int mf = 0; mf < 4; mf++) {
            uint32_t a = sb + ((wm + mf * 16 + lrow) * PITCH + k0 + lhalf) * 2;
            ldsm_x4(Ah[mf], a + AH_OFF);
            ldsm_x4(Al[mf], a + AL_OFF);
        }
#pragma unroll
        for (int np = 0; np < 2; np++) {
            uint32_t a = sb + ((k0 + lrow) * PITCH + wn + np * 16 + lhalf) * 2;
            ldsm_x4_t(Bh[np], a + BH_OFF);
            ldsm_x4_t(Bl[np], a + BL_OFF);
        }
#pragma unroll
        for (int mf = 0; mf < 4; mf++)
#pragma unroll
            for (int nf = 0; nf < 4; nf++) {
                const unsigned* bh = &Bh[nf >> 1][(nf & 1) * 2];
                const unsigned* bl = &Bl[nf >> 1][(nf & 1) * 2];
                mma_bf16(acc[mf][nf], Ah[mf], bh);
                mma_bf16(acc[mf][nf], Al[mf], bh);
                mma_bf16(acc[mf][nf], Ah[mf], bl);
            }
    }
}

// y1 + root1 fused: grid z in [0,4). z<3: relations {2z, 2z+1}.
// z==3: relations {6, 7} then root1 (bias+relu -> h1h).
__global__ void __launch_bounds__(256)
y1root_k(const float* __restrict__ A, int M, const float* __restrict__ w1,
         const float* __restrict__ root1, const float* __restrict__ bias) {
    extern __shared__ char sm[];
    const uint32_t sb = smem_u32(sm);
    const int tid = threadIdx.x;
    const int lane = tid & 31;
    const int warp = tid >> 5;
    const int wm = (warp >> 2) * 64;
    const int wn = (warp & 3) * 32;
    const int m0 = blockIdx.x * 128;
    const int lrow = lane & 15;
    const int lhalf = (lane >> 4) * 8;
    const int z = blockIdx.z;
    const int nmat = (z == 3) ? 3 : 2;

    load_A_f32(sm, A, HDIM, m0, M, tid);

#pragma unroll 1
    for (int rr = 0; rr < nmat; rr++) {
        bool is_root = (rr == 2);
        const float* B = is_root ? root1 : (w1 + (size_t)(z * 2 + rr) * HDIM * HDIM);
        load_B_f32(sm, B, tid);
        __syncthreads();

        float acc[4][4][4];
#pragma unroll
        for (int i = 0; i < 4; i++)
#pragma unroll
            for (int j = 0; j < 4; j++)
#pragma unroll
                for (int k = 0; k < 4; k++) acc[i][j][k] = 0.f;

        compute_planes(sb, wm, wn, lrow, lhalf, acc);

#pragma unroll
        for (int mf = 0; mf < 4; mf++)
#pragma unroll
            for (int nf = 0; nf < 4; nf++) {
                int r0 = m0 + wm + mf * 16 + (lane >> 2);
                int r1 = r0 + 8;
                int cl = wn + nf * 8 + (lane & 3) * 2;
                if (is_root) {
                    float b0 = bias[cl], b1v = bias[cl + 1];
                    if (r0 < M)
                        *(__half2*)(g_h1h + (size_t)r0 * HDIM + cl) =
                            __floats2half2_rn(fmaxf(acc[mf][nf][0] + b0, 0.f),
                                              fmaxf(acc[mf][nf][1] + b1v, 0.f));
                    if (r1 < M)
                        *(__half2*)(g_h1h + (size_t)r1 * HDIM + cl) =
                            __floats2half2_rn(fmaxf(acc[mf][nf][2] + b0, 0.f),
                                              fmaxf(acc[mf][nf][3] + b1v, 0.f));
                } else {
                    int r = z * 2 + rr;
                    if (r0 < M)
                        *(__half2*)(g_y1h + (size_t)r0 * (RREL * HDIM) + r * HDIM + cl) =
                            __floats2half2_rn(acc[mf][nf][0], acc[mf][nf][1]);
                    if (r1 < M)
                        *(__half2*)(g_y1h + (size_t)r1 * (RREL * HDIM) + r * HDIM + cl) =
                            __floats2half2_rn(acc[mf][nf][2], acc[mf][nf][3]);
                }
            }
        __syncthreads();
    }
}

// fused layer-2 + classifier (R11 version: reads sum2h)
__global__ void __launch_bounds__(256)
l2_k(const __half* __restrict__ sum2, const __half* __restrict__ h1,
     const float* __restrict__ w2, const float* __restrict__ root2,
     const float* __restrict__ b2, const float* __restrict__ clsw,
     const float* __restrict__ clsb, float* __restrict__ out, int M) {
    extern __shared__ char sm[];
    const uint32_t sb = smem_u32(sm);
    const int tid = threadIdx.x;
    const int lane = tid & 31;
    const int warp = tid >> 5;
    const int wm = (warp >> 2) * 64;
    const int wn = (warp & 3) * 32;
    const int m0 = blockIdx.x * 128;
    const int lrow = lane & 15;
    const int lhalf = (lane >> 4) * 8;

    float acc[4][4][4];
#pragma unroll
    for (int i = 0; i < 4; i++)
#pragma unroll
        for (int j = 0; j < 4; j++)
#pragma unroll
            for (int k = 0; k < 4; k++) acc[i][j][k] = 0.f;

#pragma unroll 1
    for (int s = 0; s < 9; s++) {
        if (s < 8) load_A_f16(sm, sum2, RREL * HDIM, s * HDIM, m0, M, tid);
        else       load_A_f16(sm, h1, HDIM, 0, m0, M, tid);
        load_B_f32(sm, (s < 8) ? (w2 + (size_t)s * HDIM * HDIM) : root2, tid);
        __syncthreads();
        compute_planes(sb, wm, wn, lrow, lhalf, acc);
        __syncthreads();
    }

    float* redA = (float*)sm;
    float* redB = (float*)sm + 512;
#pragma unroll
    for (int mf = 0; mf < 4; mf++) {
        float p0a = 0.f, p0b = 0.f, p1a = 0.f, p1b = 0.f;
#pragma unroll
        for (int nf = 0; nf < 4; nf++) {
            int cl = wn + nf * 8 + (lane & 3) * 2;
            float b0 = b2[cl], b1v = b2[cl + 1];
            float w00 = clsw[cl * 2], w01 = clsw[cl * 2 + 1];
            float w10 = clsw[(cl + 1) * 2], w11 = clsw[(cl + 1) * 2 + 1];
            float v0 = fmaxf(acc[mf][nf][0] + b0, 0.f);
            float v1 = fmaxf(acc[mf][nf][1] + b1v, 0.f);
            float v2 = fmaxf(acc[mf][nf][2] + b0, 0.f);
            float v3 = fmaxf(acc[mf][nf][3] + b1v, 0.f);
            p0a += v0 * w00 + v1 * w10; p0b += v0 * w01 + v1 * w11;
            p1a += v2 * w00 + v3 * w10; p1b += v2 * w01 + v3 * w11;
        }
#pragma unroll
        for (int o = 1; o <= 2; o <<= 1) {
            p0a += __shfl_xor_sync(0xffffffffu, p0a, o);
            p0b += __shfl_xor_sync(0xffffffffu, p0b, o);
            p1a += __shfl_xor_sync(0xffffffffu, p1a, o);
            p1b += __shfl_xor_sync(0xffffffffu, p1b, o);
        }
        if ((lane & 3) == 0) {
            int r0 = wm + mf * 16 + (lane >> 2);
            redA[r0 * 4 + (warp & 3)] = p0a;
            redB[r0 * 4 + (warp & 3)] = p0b;
            redA[(r0 + 8) * 4 + (warp & 3)] = p1a;
            redB[(r0 + 8) * 4 + (warp & 3)] = p1b;
        }
    }
    __syncthreads();
    if (tid < 128) {
        int gr = m0 + tid;
        if (gr < M) {
            float o0 = redA[tid * 4] + redA[tid * 4 + 1] + redA[tid * 4 + 2] + redA[tid * 4 + 3] + clsb[0];
            float o1 = redB[tid * 4] + redB[tid * 4 + 1] + redB[tid * 4 + 2] + redB[tid * 4 + 3] + clsb[1];
            out[gr * 2 + 0] = o0;
            out[gr * 2 + 1] = o1;
        }
    }
}

// ---------------- driver (single stream) -------------------------------------
extern "C" void kernel_launch(void* const* d_in, const int* in_sizes, int n_in,
                              void* d_out, int out_size) {
    const float* x     = (const float*)d_in[0];
    const int*   er    = (const int*)d_in[1];
    const int*   ea    = (const int*)d_in[2];
    const int*   et    = (const int*)d_in[3];
    const float* mlp_w = (const float*)d_in[4];
    const float* mlp_b = (const float*)d_in[5];
    const float* w1    = (const float*)d_in[6];
    const float* root1 = (const float*)d_in[7];
    const float* b1    = (const float*)d_in[8];
    const float* w2    = (const float*)d_in[9];
    const float* root2 = (const float*)d_in[10];
    const float* b2    = (const float*)d_in[11];
    const float* cls_w = (const float*)d_in[12];
    const float* cls_b = (const float*)d_in[13];
    int E = in_sizes[1];
    float* out = (float*)d_out;

    void *pH0, *pH1h, *pS2h;
    cudaGetSymbolAddress(&pH0, g_h0);
    cudaGetSymbolAddress(&pH1h, g_h1h);
    cudaGetSymbolAddress(&pS2h, g_sum2h);

    cudaFuncSetAttribute(y1root_k, cudaFuncAttributeMaxDynamicSharedMemorySize, MMA_SMEM);
    cudaFuncSetAttribute(l2_k, cudaFuncAttributeMaxDynamicSharedMemorySize, MMA_SMEM);

    const int GB = (NREPO + 127) / 128;   // 235

    // K1: zero counters | mlp | uroot
    front_k<<<ZBLKS + MBLKS + UBLKS, 256>>>(x, mlp_w, mlp_b, root1);
    // K2-K5: CSR construction (top-scan folded into scan_add)
    count_k<<<(E + 255) / 256, 256>>>(er, ea, et, E);
    scan_blk_all_k<<<NB1 + NB2, 1024>>>();
    scan_add_all_k<<<NB1 + NB2, 1024>>>();
    place_k<<<(E + 255) / 256, 256>>>(er, ea, et, E);
    // K6: y1 (8 relations) + root1, z=4 grid (z==3 does 3 matrices)
    y1root_k<<<dim3(GB, 1, 4), 256, MMA_SMEM>>>((const float*)pH0, NREPO, w1, root1, b1);
    // K7: layer-1 aggregation (half-warp per actor, uint4 loads)
    agg1_k<<<(NUSER * 16 + 255) / 256, 256>>>(b1, E);
    // K8: layer-2 aggregation (half-warp per bin, uint4 loads)
    agg2_k<<<((size_t)B2 * 16 + 255) / 256, 256>>>();
    // K9: fused layer-2 dense + classifier
    l2_k<<<GB, 256, MMA_SMEM>>>(
        (const __half*)pS2h, (const __half*)pH1h, w2, root2, b2, cls_w, cls_b, out, NREPO);
}

// round 14
// speedup vs baseline: 1.2796x; 1.0275x over previous
#include <cuda_runtime.h>
#include <cuda_bf16.h>
#include <cuda_fp16.h>
#include <cstdint>

#define NREPO 30000
#define NUSER 70000
#define NNODE 100000
#define RREL  8
#define HDIM  128
#define B1 (NUSER * RREL)
#define B2 (NREPO * RREL)
#define NB1 ((B1 + 1023) / 1024)
#define NB2 ((B2 + 1023) / 1024)
#define EMAX 1000000

#define MBLKS ((NREPO * HDIM + 255) / 256)
#define UBLKS (HDIM / 2)

// ---------------- scratch ----------------------------------------------------
__device__ float  g_h0[(size_t)NREPO * HDIM];
__device__ __half g_h1h[(size_t)NNODE * HDIM];
__device__ __half g_y1h[(size_t)B2 * HDIM];
__device__ __half g_sum2h[(size_t)B2 * HDIM];
__device__ float  g_uroot[HDIM];
__device__ int    g_cnt1[B1], g_off1[B1], g_cur1[B1], g_bsum1[NB1];
__device__ int    g_cnt2[B2], g_off2[B2], g_cur2[B2], g_bsum2[NB2];
__device__ int    g_perm1[EMAX];
__device__ int    g_perm2[EMAX];

// ---------------- CSR-side kernels -------------------------------------------
__global__ void zero_k() {
    int i = blockIdx.x * blockDim.x + threadIdx.x;
    if (i < B1) g_cnt1[i] = 0;
    if (i < B2) g_cnt2[i] = 0;
}

__global__ void count_k(const int* __restrict__ er, const int* __restrict__ ea,
                        const int* __restrict__ et, int E) {
    int e = blockIdx.x * blockDim.x + threadIdx.x;
    if (e >= E) return;
    atomicAdd(&g_cnt1[ea[e] * RREL + et[e]], 1);
    atomicAdd(&g_cnt2[er[e] * RREL + et[e]], 1);
}

__global__ void scan_blk_all_k() {
    __shared__ int s[1024];
    int t = threadIdx.x;
    bool first = blockIdx.x < NB1;
    int blk = first ? blockIdx.x : blockIdx.x - NB1;
    const int* cnt = first ? g_cnt1 : g_cnt2;
    int* off = first ? g_off1 : g_off2;
    int* bsum = first ? g_bsum1 : g_bsum2;
    int n = first ? B1 : B2;
    int i = blk * 1024 + t;
    int v = (i < n) ? cnt[i] : 0;
    s[t] = v;
    __syncthreads();
#pragma unroll
    for (int d = 1; d < 1024; d <<= 1) {
        int u = (t >= d) ? s[t - d] : 0;
        __syncthreads();
        s[t] += u;
        __syncthreads();
    }
    if (i < n) off[i] = s[t] - v;
    if (t == 1023) bsum[blk] = s[1023];
}

__global__ void scan_add_all_k() {
    int t = threadIdx.x;
    bool first = blockIdx.x < NB1;
    int blk = first ? blockIdx.x : blockIdx.x - NB1;
    const int* bsum = first ? g_bsum1 : g_bsum2;

    int partial = 0;
    for (int i = t; i < blk; i += 1024) partial += bsum[i];
#pragma unroll
    for (int d = 16; d; d >>= 1) partial += __shfl_xor_sync(0xffffffffu, partial, d);
    __shared__ int red[32];
    if ((t & 31) == 0) red[t >> 5] = partial;
    __syncthreads();
    __shared__ int base;
    if (t == 0) {
        int b = 0;
#pragma unroll
        for (int w = 0; w < 32; w++) b += red[w];
        base = b;
    }
    __syncthreads();
    int bs = base;

    int i = blk * 1024 + t;
    if (first) {
        if (i < B1) {
            int o = g_off1[i] + bs;
            g_off1[i] = o;
            g_cur1[i] = o;
        }
    } else {
        if (i < B2) {
            int o = g_off2[i] + bs;
            g_off2[i] = o;
            g_cur2[i] = o;
        }
    }
}

__global__ void place_k(const int* __restrict__ er, const int* __restrict__ ea,
                        const int* __restrict__ et, int E) {
    int e = blockIdx.x * blockDim.x + threadIdx.x;
    if (e >= E) return;
    int repo = er[e], actor = ea[e], t = et[e];
    int p1 = atomicAdd(&g_cur1[actor * RREL + t], 1);
    g_perm1[p1] = repo * RREL + t;
    int p2 = atomicAdd(&g_cur2[repo * RREL + t], 1);
    g_perm2[p2] = actor;
}

// ---------------- dense-front small kernel: mlp | uroot ----------------------
__global__ void mlpuroot_k(const float* __restrict__ x, const float* __restrict__ mlp_w,
                           const float* __restrict__ mlp_b, const float* __restrict__ root1) {
    int bx = blockIdx.x;
    int tid = threadIdx.x;
    if (bx < MBLKS) {
        int g = bx * 256 + tid;
        if (g >= NREPO * HDIM) return;
        int n = g >> 7, o = g & 127;
        float acc = mlp_b[o];
#pragma unroll
        for (int k = 0; k < 8; k++)
            acc = fmaf(__ldg(&x[n * 8 + k]), __ldg(&mlp_w[k * HDIM + o]), acc);
        g_h0[g] = fmaxf(acc, 0.f);
        return;
    }
    bx -= MBLKS;
    {
        int half = tid >> 7;
        int k = tid & 127;
        int o = bx * 2 + half;
        float v = fmaxf(mlp_b[k], 0.f) * root1[k * HDIM + o];
#pragma unroll
        for (int d = 16; d; d >>= 1) v += __shfl_xor_sync(0xffffffffu, v, d);
        __shared__ float s[8];
        int w = tid >> 5;
        if ((tid & 31) == 0) s[w] = v;
        __syncthreads();
        if (k == 0) g_uroot[o] = s[half * 4] + s[half * 4 + 1] + s[half * 4 + 2] + s[half * 4 + 3];
    }
}

// ---------------- aggregations ------------------------------------------------
__global__ void agg1_k(const float* __restrict__ b1, int E) {
    int hw = (blockIdx.x * blockDim.x + threadIdx.x) >> 4;
    int lane = threadIdx.x & 31;
    int lane16 = lane & 15;
    unsigned seg = 0xFFFFu << (lane & 16);
    if (hw >= NUSER) return;
    float invreg = 0.f;
    if (lane16 < RREL) {
        int d = g_cnt1[hw * RREL + lane16];
        invreg = d ? 1.0f / (float)d : 0.f;
    }
    int start = g_off1[hw * RREL];
    int end = (hw * RREL + RREL < B1) ? g_off1[hw * RREL + RREL] : E;

    float a0, a1, a2, a3, a4, a5, a6, a7;
    {
        float4 ua = *(const float4*)(g_uroot + lane16 * 8);
        float4 ub = *(const float4*)(g_uroot + lane16 * 8 + 4);
        a0 = ua.x; a1 = ua.y; a2 = ua.z; a3 = ua.w;
        a4 = ub.x; a5 = ub.y; a6 = ub.z; a7 = ub.w;
    }

#define ACC1(u, iv) { \
        float2 f0 = __half22float2(((const __half2*)&(u))[0]); \
        float2 f1 = __half22float2(((const __half2*)&(u))[1]); \
        float2 f2 = __half22float2(((const __half2*)&(u))[2]); \
        float2 f3 = __half22float2(((const __half2*)&(u))[3]); \
        a0 = fmaf(f0.x, (iv), a0); a1 = fmaf(f0.y, (iv), a1); \
        a2 = fmaf(f1.x, (iv), a2); a3 = fmaf(f1.y, (iv), a3); \
        a4 = fmaf(f2.x, (iv), a4); a5 = fmaf(f2.y, (iv), a5); \
        a6 = fmaf(f3.x, (iv), a6); a7 = fmaf(f3.y, (iv), a7); }

    int j = start;
    for (; j + 4 <= end; j += 4) {
        int p0 = __ldg(g_perm1 + j),     p1 = __ldg(g_perm1 + j + 1);
        int p2 = __ldg(g_perm1 + j + 2), p3 = __ldg(g_perm1 + j + 3);
        uint4 u0 = *(const uint4*)(g_y1h + (((size_t)p0) << 7) + lane16 * 8);
        uint4 u1 = *(const uint4*)(g_y1h + (((size_t)p1) << 7) + lane16 * 8);
        uint4 u2 = *(const uint4*)(g_y1h + (((size_t)p2) << 7) + lane16 * 8);
        uint4 u3 = *(const uint4*)(g_y1h + (((size_t)p3) << 7) + lane16 * 8);
        float iv0 = __shfl_sync(seg, invreg, (p0 & 7) | (lane & 16));
        float iv1 = __shfl_sync(seg, invreg, (p1 & 7) | (lane & 16));
        float iv2 = __shfl_sync(seg, invreg, (p2 & 7) | (lane & 16));
        float iv3 = __shfl_sync(seg, invreg, (p3 & 7) | (lane & 16));
        ACC1(u0, iv0) ACC1(u1, iv1) ACC1(u2, iv2) ACC1(u3, iv3)
    }
    for (; j < end; j++) {
        int p0 = __ldg(g_perm1 + j);
        uint4 u0 = *(const uint4*)(g_y1h + (((size_t)p0) << 7) + lane16 * 8);
        float iv0 = __shfl_sync(seg, invreg, (p0 & 7) | (lane & 16));
        ACC1(u0, iv0)
    }
#undef ACC1

    float4 ba = *(const float4*)(b1 + lane16 * 8);
    float4 bb = *(const float4*)(b1 + lane16 * 8 + 4);
    uint4 pk;
    __half2 h0 = __floats2half2_rn(fmaxf(a0 + ba.x, 0.f), fmaxf(a1 + ba.y, 0.f));
    __half2 h1 = __floats2half2_rn(fmaxf(a2 + ba.z, 0.f), fmaxf(a3 + ba.w, 0.f));
    __half2 h2 = __floats2half2_rn(fmaxf(a4 + bb.x, 0.f), fmaxf(a5 + bb.y, 0.f));
    __half2 h3 = __floats2half2_rn(fmaxf(a6 + bb.z, 0.f), fmaxf(a7 + bb.w, 0.f));
    pk.x = *(unsigned*)&h0; pk.y = *(unsigned*)&h1;
    pk.z = *(unsigned*)&h2; pk.w = *(unsigned*)&h3;
    *(uint4*)(g_h1h + (((size_t)(NREPO + hw)) << 7) + lane16 * 8) = pk;
}

__global__ void agg2_k() {
    int bin = (blockIdx.x * blockDim.x + threadIdx.x) >> 4;
    int lane16 = threadIdx.x & 15;
    if (bin >= B2) return;
    int deg = g_cnt2[bin];
    int start = g_off2[bin];
    float a0 = 0.f, a1 = 0.f, a2 = 0.f, a3 = 0.f, a4 = 0.f, a5 = 0.f, a6 = 0.f, a7 = 0.f;
#define ACC2(u) { \
        float2 f0 = __half22float2(((const __half2*)&(u))[0]); \
        float2 f1 = __half22float2(((const __half2*)&(u))[1]); \
        float2 f2 = __half22float2(((const __half2*)&(u))[2]); \
        float2 f3 = __half22float2(((const __half2*)&(u))[3]); \
        a0 += f0.x; a1 += f0.y; a2 += f1.x; a3 += f1.y; \
        a4 += f2.x; a5 += f2.y; a6 += f3.x; a7 += f3.y; }
    int j = 0;
    for (; j + 4 <= deg; j += 4) {
        int c0 = __ldg(g_perm2 + start + j);
        int c1 = __ldg(g_perm2 + start + j + 1);
        int c2 = __ldg(g_perm2 + start + j + 2);
        int c3 = __ldg(g_perm2 + start + j + 3);
        uint4 u0 = *(const uint4*)(g_h1h + (((size_t)(NREPO + c0)) << 7) + lane16 * 8);
        uint4 u1 = *(const uint4*)(g_h1h + (((size_t)(NREPO + c1)) << 7) + lane16 * 8);
        uint4 u2 = *(const uint4*)(g_h1h + (((size_t)(NREPO + c2)) << 7) + lane16 * 8);
        uint4 u3 = *(const uint4*)(g_h1h + (((size_t)(NREPO + c3)) << 7) + lane16 * 8);
        ACC2(u0) ACC2(u1) ACC2(u2) ACC2(u3)
    }
    for (; j < deg; j++) {
        int c0 = __ldg(g_perm2 + start + j);
        uint4 u0 = *(const uint4*)(g_h1h + (((size_t)(NREPO + c0)) << 7) + lane16 * 8);
        ACC2(u0)
    }
#undef ACC2
    float inv = deg ? 1.0f / (float)deg : 0.f;
    uint4 pk;
    __half2 h0 = __floats2half2_rn(a0 * inv, a1 * inv);
    __half2 h1 = __floats2half2_rn(a2 * inv, a3 * inv);
    __half2 h2 = __floats2half2_rn(a4 * inv, a5 * inv);
    __half2 h3 = __floats2half2_rn(a6 * inv, a7 * inv);
    pk.x = *(unsigned*)&h0; pk.y = *(unsigned*)&h1;
    pk.z = *(unsigned*)&h2; pk.w = *(unsigned*)&h3;
    *(uint4*)(g_sum2h + ((size_t)bin << 7) + lane16 * 8) = pk;
}

// ================= bf16 3-term tensor-core GEMM pieces =======================
#define PITCH 136
#define AH_OFF 0
#define AL_OFF 34816
#define BH_OFF 69632
#define BL_OFF 104448
#define MMA_SMEM 139264

__device__ __forceinline__ uint32_t smem_u32(const void* p) {
    uint32_t a;
    asm("{ .reg .u64 t; cvta.to.shared.u64 t, %1; cvt.u32.u64 %0, t; }" : "=r"(a) : "l"(p));
    return a;
}

__device__ __forceinline__ void ldsm_x4(unsigned r[4], uint32_t addr) {
    asm volatile("ldmatrix.sync.aligned.m8n8.x4.shared.b16 {%0,%1,%2,%3}, [%4];"
                 : "=r"(r[0]), "=r"(r[1]), "=r"(r[2]), "=r"(r[3]) : "r"(addr));
}

__device__ __forceinline__ void ldsm_x4_t(unsigned r[4], uint32_t addr) {
    asm volatile("ldmatrix.sync.aligned.m8n8.x4.trans.shared.b16 {%0,%1,%2,%3}, [%4];"
                 : "=r"(r[0]), "=r"(r[1]), "=r"(r[2]), "=r"(r[3]) : "r"(addr));
}

__device__ __forceinline__ void mma_bf16(float c[4], const unsigned a[4], const unsigned* b) {
    asm volatile(
        "mma.sync.aligned.m16n8k16.row.col.f32.bf16.bf16.f32 "
        "{%0,%1,%2,%3}, {%4,%5,%6,%7}, {%8,%9}, {%0,%1,%2,%3};"
        : "+f"(c[0]), "+f"(c[1]), "+f"(c[2]), "+f"(c[3])
        : "r"(a[0]), "r"(a[1]), "r"(a[2]), "r"(a[3]), "r"(b[0]), "r"(b[1]));
}

__device__ __forceinline__ void sp_bf(float x, unsigned short& h, unsigned short& l) {
    __nv_bfloat16 hb = __float2bfloat16_rn(x);
    h = __bfloat16_as_ushort(hb);
    l = __bfloat16_as_ushort(__float2bfloat16_rn(x - __bfloat162float(hb)));
}

__device__ __forceinline__ void store_planes(char* sm, int plane_off_h, int plane_off_l,
                                             int row, int c4, float4 f) {
    unsigned short h0, h1, h2, h3, l0, l1, l2, l3;
    sp_bf(f.x, h0, l0); sp_bf(f.y, h1, l1); sp_bf(f.z, h2, l2); sp_bf(f.w, h3, l3);
    int off = (row * PITCH + c4) * 2;
    *(uint2*)(sm + plane_off_h + off) = make_uint2((unsigned)h0 | ((unsigned)h1 << 16),
                                                   (unsigned)h2 | ((unsigned)h3 << 16));
    *(uint2*)(sm + plane_off_l + off) = make_uint2((unsigned)l0 | ((unsigned)l1 << 16),
                                                   (unsigned)l2 | ((unsigned)l3 << 16));
}

__device__ __forceinline__ void load_A_f32(char* sm, const float* __restrict__ A, int lda,
                                           int m0, int M, int tid) {
#pragma unroll
    for (int it = 0; it < 16; it++) {
        int v = tid + it * 256;
        int row = v >> 5;
        int c4 = (v & 31) * 4;
        float4 fa = (m0 + row < M) ? *(const float4*)(A + (size_t)(m0 + row) * lda + c4)
                                   : make_float4(0.f, 0.f, 0.f, 0.f);
        store_planes(sm, AH_OFF, AL_OFF, row, c4, fa);
    }
}

__device__ __forceinline__ void load_A_f16(char* sm, const __half* __restrict__ A, int lda,
                                           int cO, int m0, int M, int tid) {
#pragma unroll
    for (int it = 0; it < 16; it++) {
        int v = tid + it * 256;
        int row = v >> 5;
        int c4 = (v & 31) * 4;
        float4 fa = make_float4(0.f, 0.f, 0.f, 0.f);
        if (m0 + row < M) {
            uint2 u = *(const uint2*)(A + (size_t)(m0 + row) * lda + cO + c4);
            float2 lo = __half22float2(((const __half2*)&u)[0]);
            float2 hi = __half22float2(((const __half2*)&u)[1]);
            fa = make_float4(lo.x, lo.y, hi.x, hi.y);
        }
        store_planes(sm, AH_OFF, AL_OFF, row, c4, fa);
    }
}

__device__ __forceinline__ void load_B_f32(char* sm, const float* __restrict__ B, int tid) {
#pragma unroll
    for (int it = 0; it < 16; it++) {
        int v = tid + it * 256;
        int row = v >> 5;
        int c4 = (v & 31) * 4;
        float4 fb = *(const float4*)(B + (size_t)row * 128 + c4);
        store_planes(sm, BH_OFF, BL_OFF, row, c4, fb);
    }
}

__device__ __forceinline__ void compute_planes(uint32_t sb, int wm, int wn, int lrow,
                                               int lhalf, float (&acc)[4][4][4]) {
#pragma unroll 1
    for (int kc = 0; kc < 8; kc++) {
        int k0 = kc * 16;
        unsigned Ah[4][4], Al[4][4], Bh[2][4], Bl[2][4];
#pragma unroll
        for (int mf = 0; mf < 4; mf++) {
            uint32_t a = sb + ((wm + mf * 16 + lrow) * PITCH + k0 + lhalf) * 2;
            ldsm_x4(Ah[mf], a + AH_OFF);
            ldsm_x4(Al[mf], a + AL_OFF);
        }
#pragma unroll
        for (int np = 0; np < 2; np++) {
            uint32_t a = sb + ((k0 + lrow) * PITCH + wn + np * 16 + lhalf) * 2;
            ldsm_x4_t(Bh[np], a + BH_OFF);
            ldsm_x4_t(Bl[np], a + BL_OFF);
        }
#pragma unroll
        for (int mf = 0; mf < 4; mf++)
#pragma unroll
            for (int nf = 0; nf < 4; nf++) {
                const unsigned* bh = &Bh[nf >> 1][(nf & 1) * 2];
                const unsigned* bl = &Bl[nf >> 1][(nf & 1) * 2];
                mma_bf16(acc[mf][nf], Ah[mf], bh);
                mma_bf16(acc[mf][nf], Al[mf], bh);
                mma_bf16(acc[mf][nf], Ah[mf], bl);
            }
    }
}

// y1 + root1 fused: grid z in [0,4). z<3: relations {2z, 2z+1}.
// z==3: relations {6, 7} then root1 (bias+relu -> h1h).
__global__ void __launch_bounds__(256)
y1root_k(const float* __restrict__ A, int M, const float* __restrict__ w1,
         const float* __restrict__ root1, const float* __restrict__ bias) {
    extern __shared__ char sm[];
    const uint32_t sb = smem_u32(sm);
    const int tid = threadIdx.x;
    const int lane = tid & 31;
    const int warp = tid >> 5;
    const int wm = (warp >> 2) * 64;
    const int wn = (warp & 3) * 32;
    const int m0 = blockIdx.x * 128;
    const int lrow = lane & 15;
    const int lhalf = (lane >> 4) * 8;
    const int z = blockIdx.z;
    const int nmat = (z == 3) ? 3 : 2;

    load_A_f32(sm, A, HDIM, m0, M, tid);

#pragma unroll 1
    for (int rr = 0; rr < nmat; rr++) {
        bool is_root = (rr == 2);
        const float* B = is_root ? root1 : (w1 + (size_t)(z * 2 + rr) * HDIM * HDIM);
        load_B_f32(sm, B, tid);
        __syncthreads();

        float acc[4][4][4];
#pragma unroll
        for (int i = 0; i < 4; i++)
#pragma unroll
            for (int j = 0; j < 4; j++)
#pragma unroll
                for (int k = 0; k < 4; k++) acc[i][j][k] = 0.f;

        compute_planes(sb, wm, wn, lrow, lhalf, acc);

#pragma unroll
        for (int mf = 0; mf < 4; mf++)
#pragma unroll
            for (int nf = 0; nf < 4; nf++) {
                int r0 = m0 + wm + mf * 16 + (lane >> 2);
                int r1 = r0 + 8;
                int cl = wn + nf * 8 + (lane & 3) * 2;
                if (is_root) {
                    float b0 = bias[cl], b1v = bias[cl + 1];
                    if (r0 < M)
                        *(__half2*)(g_h1h + (size_t)r0 * HDIM + cl) =
                            __floats2half2_rn(fmaxf(acc[mf][nf][0] + b0, 0.f),
                                              fmaxf(acc[mf][nf][1] + b1v, 0.f));
                    if (r1 < M)
                        *(__half2*)(g_h1h + (size_t)r1 * HDIM + cl) =
                            __floats2half2_rn(fmaxf(acc[mf][nf][2] + b0, 0.f),
                                              fmaxf(acc[mf][nf][3] + b1v, 0.f));
                } else {
                    int r = z * 2 + rr;
                    if (r0 < M)
                        *(__half2*)(g_y1h + (size_t)r0 * (RREL * HDIM) + r * HDIM + cl) =
                            __floats2half2_rn(acc[mf][nf][0], acc[mf][nf][1]);
                    if (r1 < M)
                        *(__half2*)(g_y1h + (size_t)r1 * (RREL * HDIM) + r * HDIM + cl) =
                            __floats2half2_rn(acc[mf][nf][2], acc[mf][nf][3]);
                }
            }
        __syncthreads();
    }
}

// fused layer-2 + classifier
__global__ void __launch_bounds__(256)
l2_k(const __half* __restrict__ sum2, const __half* __restrict__ h1,
     const float* __restrict__ w2, const float* __restrict__ root2,
     const float* __restrict__ b2, const float* __restrict__ clsw,
     const float* __restrict__ clsb, float* __restrict__ out, int M) {
    extern __shared__ char sm[];
    const uint32_t sb = smem_u32(sm);
    const int tid = threadIdx.x;
    const int lane = tid & 31;
    const int warp = tid >> 5;
    const int wm = (warp >> 2) * 64;
    const int wn = (warp & 3) * 32;
    const int m0 = blockIdx.x * 128;
    const int lrow = lane & 15;
    const int lhalf = (lane >> 4) * 8;

    float acc[4][4][4];
#pragma unroll
    for (int i = 0; i < 4; i++)
#pragma unroll
        for (int j = 0; j < 4; j++)
#pragma unroll
            for (int k = 0; k < 4; k++) acc[i][j][k] = 0.f;

#pragma unroll 1
    for (int s = 0; s < 9; s++) {
        if (s < 8) load_A_f16(sm, sum2, RREL * HDIM, s * HDIM, m0, M, tid);
        else       load_A_f16(sm, h1, HDIM, 0, m0, M, tid);
        load_B_f32(sm, (s < 8) ? (w2 + (size_t)s * HDIM * HDIM) : root2, tid);
        __syncthreads();
        compute_planes(sb, wm, wn, lrow, lhalf, acc);
        __syncthreads();
    }

    float* redA = (float*)sm;
    float* redB = (float*)sm + 512;
#pragma unroll
    for (int mf = 0; mf < 4; mf++) {
        float p0a = 0.f, p0b = 0.f, p1a = 0.f, p1b = 0.f;
#pragma unroll
        for (int nf = 0; nf < 4; nf++) {
            int cl = wn + nf * 8 + (lane & 3) * 2;
            float b0 = b2[cl], b1v = b2[cl + 1];
            float w00 = clsw[cl * 2], w01 = clsw[cl * 2 + 1];
            float w10 = clsw[(cl + 1) * 2], w11 = clsw[(cl + 1) * 2 + 1];
            float v0 = fmaxf(acc[mf][nf][0] + b0, 0.f);
            float v1 = fmaxf(acc[mf][nf][1] + b1v, 0.f);
            float v2 = fmaxf(acc[mf][nf][2] + b0, 0.f);
            float v3 = fmaxf(acc[mf][nf][3] + b1v, 0.f);
            p0a += v0 * w00 + v1 * w10; p0b += v0 * w01 + v1 * w11;
            p1a += v2 * w00 + v3 * w10; p1b += v2 * w01 + v3 * w11;
        }
#pragma unroll
        for (int o = 1; o <= 2; o <<= 1) {
            p0a += __shfl_xor_sync(0xffffffffu, p0a, o);
            p0b += __shfl_xor_sync(0xffffffffu, p0b, o);
            p1a += __shfl_xor_sync(0xffffffffu, p1a, o);
            p1b += __shfl_xor_sync(0xffffffffu, p1b, o);
        }
        if ((lane & 3) == 0) {
            int r0 = wm + mf * 16 + (lane >> 2);
            redA[r0 * 4 + (warp & 3)] = p0a;
            redB[r0 * 4 + (warp & 3)] = p0b;
            redA[(r0 + 8) * 4 + (warp & 3)] = p1a;
            redB[(r0 + 8) * 4 + (warp & 3)] = p1b;
        }
    }
    __syncthreads();
    if (tid < 128) {
        int gr = m0 + tid;
        if (gr < M) {
            float o0 = redA[tid * 4] + redA[tid * 4 + 1] + redA[tid * 4 + 2] + redA[tid * 4 + 3] + clsb[0];
            float o1 = redB[tid * 4] + redB[tid * 4 + 1] + redB[tid * 4 + 2] + redB[tid * 4 + 3] + clsb[1];
            out[gr * 2 + 0] = o0;
            out[gr * 2 + 1] = o1;
        }
    }
}

// ---------------- driver: fork/join two independent chains --------------------
static cudaStream_t g_s2 = nullptr;
static cudaEvent_t  g_evF = nullptr, g_evJ = nullptr;

extern "C" void kernel_launch(void* const* d_in, const int* in_sizes, int n_in,
                              void* d_out, int out_size) {
    const float* x     = (const float*)d_in[0];
    const int*   er    = (const int*)d_in[1];
    const int*   ea    = (const int*)d_in[2];
    const int*   et    = (const int*)d_in[3];
    const float* mlp_w = (const float*)d_in[4];
    const float* mlp_b = (const float*)d_in[5];
    const float* w1    = (const float*)d_in[6];
    const float* root1 = (const float*)d_in[7];
    const float* b1    = (const float*)d_in[8];
    const float* w2    = (const float*)d_in[9];
    const float* root2 = (const float*)d_in[10];
    const float* b2    = (const float*)d_in[11];
    const float* cls_w = (const float*)d_in[12];
    const float* cls_b = (const float*)d_in[13];
    int E = in_sizes[1];
    float* out = (float*)d_out;

    if (!g_s2) {   // first call is the uncaptured correctness run
        cudaStreamCreateWithFlags(&g_s2, cudaStreamNonBlocking);
        cudaEventCreateWithFlags(&g_evF, cudaEventDisableTiming);
        cudaEventCreateWithFlags(&g_evJ, cudaEventDisableTiming);
    }

    void *pH0, *pH1h, *pS2h;
    cudaGetSymbolAddress(&pH0, g_h0);
    cudaGetSymbolAddress(&pH1h, g_h1h);
    cudaGetSymbolAddress(&pS2h, g_sum2h);

    cudaFuncSetAttribute(y1root_k, cudaFuncAttributeMaxDynamicSharedMemorySize, MMA_SMEM);
    cudaFuncSetAttribute(l2_k, cudaFuncAttributeMaxDynamicSharedMemorySize, MMA_SMEM);

    const int GB = (NREPO + 127) / 128;   // 235

    // ---- fork: dense front (independent of CSR) on side stream ----
    cudaEventRecord(g_evF, 0);
    cudaStreamWaitEvent(g_s2, g_evF, 0);
    mlpuroot_k<<<MBLKS + UBLKS, 256, 0, g_s2>>>(x, mlp_w, mlp_b, root1);
    y1root_k<<<dim3(GB, 1, 4), 256, MMA_SMEM, g_s2>>>((const float*)pH0, NREPO, w1, root1, b1);
    cudaEventRecord(g_evJ, g_s2);

    // ---- CSR chain on main stream (overlaps dense front) ----
    zero_k<<<(B1 + 255) / 256, 256>>>();
    count_k<<<(E + 255) / 256, 256>>>(er, ea, et, E);
    scan_blk_all_k<<<NB1 + NB2, 1024>>>();
    scan_add_all_k<<<NB1 + NB2, 1024>>>();
    place_k<<<(E + 255) / 256, 256>>>(er, ea, et, E);

    // ---- join ----
    cudaStreamWaitEvent(0, g_evJ, 0);

    // layer-1 aggregation
    agg1_k<<<(NUSER * 16 + 255) / 256, 256>>>(b1, E);
    // layer-2 aggregation
    agg2_k<<<((size_t)B2 * 16 + 255) / 256, 256>>>();
    // fused layer-2 dense + classifier
    l2_k<<<GB, 256, MMA_SMEM>>>(
        (const __half*)pS2h, (const __half*)pH1h, w2, root2, b2, cls_w, cls_b, out, NREPO);
}

// round 15
// speedup vs baseline: 2.0069x; 1.5684x over previous
#include <cuda_runtime.h>
#include <cuda_fp16.h>
#include <cstdint>

#define NREPO 30000
#define NUSER 70000
#define NNODE 100000
#define RREL  8
#define HDIM  128
#define B1 (NUSER * RREL)
#define B2 (NREPO * RREL)
#define NB1 ((B1 + 1023) / 1024)
#define NB2 ((B2 + 1023) / 1024)
#define EMAX 1000000

#define MBLKS ((NREPO * HDIM + 255) / 256)
#define UBLKS (HDIM / 2)

// ---------------- scratch ----------------------------------------------------
__device__ float  g_h0[(size_t)NREPO * HDIM];
__device__ __half g_h1h[(size_t)NNODE * HDIM];
__device__ __half g_y1h[(size_t)B2 * HDIM];
__device__ __half g_sum2h[(size_t)B2 * HDIM];
__device__ float  g_uroot[HDIM];
__device__ int    g_cnt1[B1], g_off1[B1], g_cur1[B1], g_bsum1[NB1];
__device__ int    g_cnt2[B2], g_off2[B2], g_cur2[B2], g_bsum2[NB2];
__device__ int    g_perm1[EMAX];
__device__ int    g_perm2[EMAX];

// ---------------- CSR-side kernels -------------------------------------------
__global__ void zero_k() {
    int i = blockIdx.x * blockDim.x + threadIdx.x;
    if (i < B1) g_cnt1[i] = 0;
    if (i < B2) g_cnt2[i] = 0;
}

__global__ void count_k(const int* __restrict__ er, const int* __restrict__ ea,
                        const int* __restrict__ et, int E) {
    int e = blockIdx.x * blockDim.x + threadIdx.x;
    if (e >= E) return;
    atomicAdd(&g_cnt1[ea[e] * RREL + et[e]], 1);
    atomicAdd(&g_cnt2[er[e] * RREL + et[e]], 1);
}

__global__ void scan_blk_all_k() {
    __shared__ int s[1024];
    int t = threadIdx.x;
    bool first = blockIdx.x < NB1;
    int blk = first ? blockIdx.x : blockIdx.x - NB1;
    const int* cnt = first ? g_cnt1 : g_cnt2;
    int* off = first ? g_off1 : g_off2;
    int* bsum = first ? g_bsum1 : g_bsum2;
    int n = first ? B1 : B2;
    int i = blk * 1024 + t;
    int v = (i < n) ? cnt[i] : 0;
    s[t] = v;
    __syncthreads();
#pragma unroll
    for (int d = 1; d < 1024; d <<= 1) {
        int u = (t >= d) ? s[t - d] : 0;
        __syncthreads();
        s[t] += u;
        __syncthreads();
    }
    if (i < n) off[i] = s[t] - v;
    if (t == 1023) bsum[blk] = s[1023];
}

__global__ void scan_add_all_k() {
    int t = threadIdx.x;
    bool first = blockIdx.x < NB1;
    int blk = first ? blockIdx.x : blockIdx.x - NB1;
    const int* bsum = first ? g_bsum1 : g_bsum2;

    int partial = 0;
    for (int i = t; i < blk; i += 1024) partial += bsum[i];
#pragma unroll
    for (int d = 16; d; d >>= 1) partial += __shfl_xor_sync(0xffffffffu, partial, d);
    __shared__ int red[32];
    if ((t & 31) == 0) red[t >> 5] = partial;
    __syncthreads();
    __shared__ int base;
    if (t == 0) {
        int b = 0;
#pragma unroll
        for (int w = 0; w < 32; w++) b += red[w];
        base = b;
    }
    __syncthreads();
    int bs = base;

    int i = blk * 1024 + t;
    if (first) {
        if (i < B1) {
            int o = g_off1[i] + bs;
            g_off1[i] = o;
            g_cur1[i] = o;
        }
    } else {
        if (i < B2) {
            int o = g_off2[i] + bs;
            g_off2[i] = o;
            g_cur2[i] = o;
        }
    }
}

__global__ void place_k(const int* __restrict__ er, const int* __restrict__ ea,
                        const int* __restrict__ et, int E) {
    int e = blockIdx.x * blockDim.x + threadIdx.x;
    if (e >= E) return;
    int repo = er[e], actor = ea[e], t = et[e];
    int p1 = atomicAdd(&g_cur1[actor * RREL + t], 1);
    g_perm1[p1] = repo * RREL + t;
    int p2 = atomicAdd(&g_cur2[repo * RREL + t], 1);
    g_perm2[p2] = actor;
}

// ---------------- dense-front small kernel: mlp | uroot ----------------------
__global__ void mlpuroot_k(const float* __restrict__ x, const float* __restrict__ mlp_w,
                           const float* __restrict__ mlp_b, const float* __restrict__ root1) {
    int bx = blockIdx.x;
    int tid = threadIdx.x;
    if (bx < MBLKS) {
        int g = bx * 256 + tid;
        if (g >= NREPO * HDIM) return;
        int n = g >> 7, o = g & 127;
        float acc = mlp_b[o];
#pragma unroll
        for (int k = 0; k < 8; k++)
            acc = fmaf(__ldg(&x[n * 8 + k]), __ldg(&mlp_w[k * HDIM + o]), acc);
        g_h0[g] = fmaxf(acc, 0.f);
        return;
    }
    bx -= MBLKS;
    {
        int half = tid >> 7;
        int k = tid & 127;
        int o = bx * 2 + half;
        float v = fmaxf(mlp_b[k], 0.f) * root1[k * HDIM + o];
#pragma unroll
        for (int d = 16; d; d >>= 1) v += __shfl_xor_sync(0xffffffffu, v, d);
        __shared__ float s[8];
        int w = tid >> 5;
        if ((tid & 31) == 0) s[w] = v;
        __syncthreads();
        if (k == 0) g_uroot[o] = s[half * 4] + s[half * 4 + 1] + s[half * 4 + 2] + s[half * 4 + 3];
    }
}

// ---------------- aggregations ------------------------------------------------
__global__ void agg1_k(const float* __restrict__ b1, int E) {
    int hw = (blockIdx.x * blockDim.x + threadIdx.x) >> 4;
    int lane = threadIdx.x & 31;
    int lane16 = lane & 15;
    unsigned seg = 0xFFFFu << (lane & 16);
    if (hw >= NUSER) return;
    float invreg = 0.f;
    if (lane16 < RREL) {
        int d = g_cnt1[hw * RREL + lane16];
        invreg = d ? 1.0f / (float)d : 0.f;
    }
    int start = g_off1[hw * RREL];
    int end = (hw * RREL + RREL < B1) ? g_off1[hw * RREL + RREL] : E;

    float a0, a1, a2, a3, a4, a5, a6, a7;
    {
        float4 ua = *(const float4*)(g_uroot + lane16 * 8);
        float4 ub = *(const float4*)(g_uroot + lane16 * 8 + 4);
        a0 = ua.x; a1 = ua.y; a2 = ua.z; a3 = ua.w;
        a4 = ub.x; a5 = ub.y; a6 = ub.z; a7 = ub.w;
    }

#define ACC1(u, iv) { \
        float2 f0 = __half22float2(((const __half2*)&(u))[0]); \
        float2 f1 = __half22float2(((const __half2*)&(u))[1]); \
        float2 f2 = __half22float2(((const __half2*)&(u))[2]); \
        float2 f3 = __half22float2(((const __half2*)&(u))[3]); \
        a0 = fmaf(f0.x, (iv), a0); a1 = fmaf(f0.y, (iv), a1); \
        a2 = fmaf(f1.x, (iv), a2); a3 = fmaf(f1.y, (iv), a3); \
        a4 = fmaf(f2.x, (iv), a4); a5 = fmaf(f2.y, (iv), a5); \
        a6 = fmaf(f3.x, (iv), a6); a7 = fmaf(f3.y, (iv), a7); }

    int j = start;
    for (; j + 4 <= end; j += 4) {
        int p0 = __ldg(g_perm1 + j),     p1 = __ldg(g_perm1 + j + 1);
        int p2 = __ldg(g_perm1 + j + 2), p3 = __ldg(g_perm1 + j + 3);
        uint4 u0 = *(const uint4*)(g_y1h + (((size_t)p0) << 7) + lane16 * 8);
        uint4 u1 = *(const uint4*)(g_y1h + (((size_t)p1) << 7) + lane16 * 8);
        uint4 u2 = *(const uint4*)(g_y1h + (((size_t)p2) << 7) + lane16 * 8);
        uint4 u3 = *(const uint4*)(g_y1h + (((size_t)p3) << 7) + lane16 * 8);
        float iv0 = __shfl_sync(seg, invreg, (p0 & 7) | (lane & 16));
        float iv1 = __shfl_sync(seg, invreg, (p1 & 7) | (lane & 16));
        float iv2 = __shfl_sync(seg, invreg, (p2 & 7) | (lane & 16));
        float iv3 = __shfl_sync(seg, invreg, (p3 & 7) | (lane & 16));
        ACC1(u0, iv0) ACC1(u1, iv1) ACC1(u2, iv2) ACC1(u3, iv3)
    }
    for (; j < end; j++) {
        int p0 = __ldg(g_perm1 + j);
        uint4 u0 = *(const uint4*)(g_y1h + (((size_t)p0) << 7) + lane16 * 8);
        float iv0 = __shfl_sync(seg, invreg, (p0 & 7) | (lane & 16));
        ACC1(u0, iv0)
    }
#undef ACC1

    float4 ba = *(const float4*)(b1 + lane16 * 8);
    float4 bb = *(const float4*)(b1 + lane16 * 8 + 4);
    uint4 pk;
    __half2 h0 = __floats2half2_rn(fmaxf(a0 + ba.x, 0.f), fmaxf(a1 + ba.y, 0.f));
    __half2 h1 = __floats2half2_rn(fmaxf(a2 + ba.z, 0.f), fmaxf(a3 + ba.w, 0.f));
    __half2 h2 = __floats2half2_rn(fmaxf(a4 + bb.x, 0.f), fmaxf(a5 + bb.y, 0.f));
    __half2 h3 = __floats2half2_rn(fmaxf(a6 + bb.z, 0.f), fmaxf(a7 + bb.w, 0.f));
    pk.x = *(unsigned*)&h0; pk.y = *(unsigned*)&h1;
    pk.z = *(unsigned*)&h2; pk.w = *(unsigned*)&h3;
    *(uint4*)(g_h1h + (((size_t)(NREPO + hw)) << 7) + lane16 * 8) = pk;
}

__global__ void agg2_k() {
    int bin = (blockIdx.x * blockDim.x + threadIdx.x) >> 4;
    int lane16 = threadIdx.x & 15;
    if (bin >= B2) return;
    int deg = g_cnt2[bin];
    int start = g_off2[bin];
    float a0 = 0.f, a1 = 0.f, a2 = 0.f, a3 = 0.f, a4 = 0.f, a5 = 0.f, a6 = 0.f, a7 = 0.f;
#define ACC2(u) { \
        float2 f0 = __half22float2(((const __half2*)&(u))[0]); \
        float2 f1 = __half22float2(((const __half2*)&(u))[1]); \
        float2 f2 = __half22float2(((const __half2*)&(u))[2]); \
        float2 f3 = __half22float2(((const __half2*)&(u))[3]); \
        a0 += f0.x; a1 += f0.y; a2 += f1.x; a3 += f1.y; \
        a4 += f2.x; a5 += f2.y; a6 += f3.x; a7 += f3.y; }
    int j = 0;
    for (; j + 4 <= deg; j += 4) {
        int c0 = __ldg(g_perm2 + start + j);
        int c1 = __ldg(g_perm2 + start + j + 1);
        int c2 = __ldg(g_perm2 + start + j + 2);
        int c3 = __ldg(g_perm2 + start + j + 3);
        uint4 u0 = *(const uint4*)(g_h1h + (((size_t)(NREPO + c0)) << 7) + lane16 * 8);
        uint4 u1 = *(const uint4*)(g_h1h + (((size_t)(NREPO + c1)) << 7) + lane16 * 8);
        uint4 u2 = *(const uint4*)(g_h1h + (((size_t)(NREPO + c2)) << 7) + lane16 * 8);
        uint4 u3 = *(const uint4*)(g_h1h + (((size_t)(NREPO + c3)) << 7) + lane16 * 8);
        ACC2(u0) ACC2(u1) ACC2(u2) ACC2(u3)
    }
    for (; j < deg; j++) {
        int c0 = __ldg(g_perm2 + start + j);
        uint4 u0 = *(const uint4*)(g_h1h + (((size_t)(NREPO + c0)) << 7) + lane16 * 8);
        ACC2(u0)
    }
#undef ACC2
    float inv = deg ? 1.0f / (float)deg : 0.f;
    uint4 pk;
    __half2 h0 = __floats2half2_rn(a0 * inv, a1 * inv);
    __half2 h1 = __floats2half2_rn(a2 * inv, a3 * inv);
    __half2 h2 = __floats2half2_rn(a4 * inv, a5 * inv);
    __half2 h3 = __floats2half2_rn(a6 * inv, a7 * inv);
    pk.x = *(unsigned*)&h0; pk.y = *(unsigned*)&h1;
    pk.z = *(unsigned*)&h2; pk.w = *(unsigned*)&h3;
    *(uint4*)(g_sum2h + ((size_t)bin << 7) + lane16 * 8) = pk;
}

// ================= fp16 tensor-core GEMM pieces ==============================
#define PITCH 136
#define PLANE 34816                 // bytes per 128 x PITCH fp16 plane
#define SMEM_Y1 (3 * PLANE + 128)   // AH, AL, BH
#define SMEM_L2 (2 * PLANE + 128)   // A, B

__device__ __forceinline__ uint32_t smem_u32(const void* p) {
    uint32_t a;
    asm("{ .reg .u64 t; cvta.to.shared.u64 t, %1; cvt.u32.u64 %0, t; }" : "=r"(a) : "l"(p));
    return a;
}

__device__ __forceinline__ void ldsm_x4(unsigned r[4], uint32_t addr) {
    asm volatile("ldmatrix.sync.aligned.m8n8.x4.shared.b16 {%0,%1,%2,%3}, [%4];"
                 : "=r"(r[0]), "=r"(r[1]), "=r"(r[2]), "=r"(r[3]) : "r"(addr));
}

__device__ __forceinline__ void ldsm_x4_t(unsigned r[4], uint32_t addr) {
    asm volatile("ldmatrix.sync.aligned.m8n8.x4.trans.shared.b16 {%0,%1,%2,%3}, [%4];"
                 : "=r"(r[0]), "=r"(r[1]), "=r"(r[2]), "=r"(r[3]) : "r"(addr));
}

__device__ __forceinline__ void mma_f16(float c[4], const unsigned a[4], const unsigned* b) {
    asm volatile(
        "mma.sync.aligned.m16n8k16.row.col.f32.f16.f16.f32 "
        "{%0,%1,%2,%3}, {%4,%5,%6,%7}, {%8,%9}, {%0,%1,%2,%3};"
        : "+f"(c[0]), "+f"(c[1]), "+f"(c[2]), "+f"(c[3])
        : "r"(a[0]), "r"(a[1]), "r"(a[2]), "r"(a[3]), "r"(b[0]), "r"(b[1]));
}

// fp16 hi/lo split of fp32 (captures ~22 bits)
__device__ __forceinline__ void sp_h(float x, unsigned short& h, unsigned short& l) {
    __half hh = __float2half_rn(x);
    h = __half_as_ushort(hh);
    l = __half_as_ushort(__float2half_rn(x - __half2float(hh)));
}

// A fp32 -> hi/lo fp16 planes (offsets 0, PLANE)
__device__ __forceinline__ void load_A_split(char* sm, const float* __restrict__ A, int lda,
                                             int m0, int M, int tid) {
#pragma unroll
    for (int it = 0; it < 16; it++) {
        int v = tid + it * 256;
        int row = v >> 5;
        int c4 = (v & 31) * 4;
        float4 fa = (m0 + row < M) ? *(const float4*)(A + (size_t)(m0 + row) * lda + c4)
                                   : make_float4(0.f, 0.f, 0.f, 0.f);
        unsigned short h0, h1, h2, h3, l0, l1, l2, l3;
        sp_h(fa.x, h0, l0); sp_h(fa.y, h1, l1); sp_h(fa.z, h2, l2); sp_h(fa.w, h3, l3);
        int off = (row * PITCH + c4) * 2;
        *(uint2*)(sm + off) = make_uint2((unsigned)h0 | ((unsigned)h1 << 16),
                                         (unsigned)h2 | ((unsigned)h3 << 16));
        *(uint2*)(sm + PLANE + off) = make_uint2((unsigned)l0 | ((unsigned)l1 << 16),
                                                 (unsigned)l2 | ((unsigned)l3 << 16));
    }
}

// B fp32 -> single fp16 plane at byte offset po
__device__ __forceinline__ void load_B_h(char* sm, int po, const float* __restrict__ B, int tid) {
#pragma unroll
    for (int it = 0; it < 16; it++) {
        int v = tid + it * 256;
        int row = v >> 5;
        int c4 = (v & 31) * 4;
        float4 fb = *(const float4*)(B + (size_t)row * 128 + c4);
        __half2 p0 = __floats2half2_rn(fb.x, fb.y);
        __half2 p1 = __floats2half2_rn(fb.z, fb.w);
        int off = (row * PITCH + c4) * 2;
        *(uint2*)(sm + po + off) = make_uint2(*(unsigned*)&p0, *(unsigned*)&p1);
    }
}

// A fp16 -> direct copy into plane 0
__device__ __forceinline__ void load_A_copy(char* sm, const __half* __restrict__ A, int lda,
                                            int cO, int m0, int M, int tid) {
#pragma unroll
    for (int it = 0; it < 16; it++) {
        int v = tid + it * 256;
        int row = v >> 5;
        int c4 = (v & 31) * 4;
        uint2 u = make_uint2(0u, 0u);
        if (m0 + row < M) u = *(const uint2*)(A + (size_t)(m0 + row) * lda + cO + c4);
        *(uint2*)(sm + (row * PITCH + c4) * 2) = u;
    }
}

// 2-term compute: (Ah + Al) @ B   (planes: 0=Ah, PLANE=Al, 2*PLANE=B)
__device__ __forceinline__ void compute_2t(uint32_t sb, int wm, int wn, int lrow,
                                           int lhalf, float (&acc)[4][4][4]) {
#pragma unroll 1
    for (int kc = 0; kc < 8; kc++) {
        int k0 = kc * 16;
        unsigned Ah[4][4], Al[4][4], Bf[2][4];
#pragma unroll
        for (int mf = 0; mf < 4; mf++) {
            uint32_t a = sb + ((wm + mf * 16 + lrow) * PITCH + k0 + lhalf) * 2;
            ldsm_x4(Ah[mf], a);
            ldsm_x4(Al[mf], a + PLANE);
        }
#pragma unroll
        for (int np = 0; np < 2; np++) {
            uint32_t a = sb + ((k0 + lrow) * PITCH + wn + np * 16 + lhalf) * 2 + 2 * PLANE;
            ldsm_x4_t(Bf[np], a);
        }
#pragma unroll
        for (int mf = 0; mf < 4; mf++)
#pragma unroll
            for (int nf = 0; nf < 4; nf++) {
                const unsigned* b = &Bf[nf >> 1][(nf & 1) * 2];
                mma_f16(acc[mf][nf], Ah[mf], b);
                mma_f16(acc[mf][nf], Al[mf], b);
            }
    }
}

// 1-term compute: A @ B   (planes: 0=A, PLANE=B)
__device__ __forceinline__ void compute_1t(uint32_t sb, int wm, int wn, int lrow,
                                           int lhalf, float (&acc)[4][4][4]) {
#pragma unroll 1
    for (int kc = 0; kc < 8; kc++) {
        int k0 = kc * 16;
        unsigned Af[4][4], Bf[2][4];
#pragma unroll
        for (int mf = 0; mf < 4; mf++)
            ldsm_x4(Af[mf], sb + ((wm + mf * 16 + lrow) * PITCH + k0 + lhalf) * 2);
#pragma unroll
        for (int np = 0; np < 2; np++)
            ldsm_x4_t(Bf[np], sb + ((k0 + lrow) * PITCH + wn + np * 16 + lhalf) * 2 + PLANE);
#pragma unroll
        for (int mf = 0; mf < 4; mf++)
#pragma unroll
            for (int nf = 0; nf < 4; nf++)
                mma_f16(acc[mf][nf], Af[mf], &Bf[nf >> 1][(nf & 1) * 2]);
    }
}

// y1 + root1 fused: grid z in [0,4). z<3: relations {2z, 2z+1}.
// z==3: relations {6, 7} then root1 (bias+relu -> h1h).
__global__ void __launch_bounds__(256)
y1root_k(const float* __restrict__ A, int M, const float* __restrict__ w1,
         const float* __restrict__ root1, const float* __restrict__ bias) {
    extern __shared__ char sm[];
    const uint32_t sb = smem_u32(sm);
    const int tid = threadIdx.x;
    const int lane = tid & 31;
    const int warp = tid >> 5;
    const int wm = (warp >> 2) * 64;
    const int wn = (warp & 3) * 32;
    const int m0 = blockIdx.x * 128;
    const int lrow = lane & 15;
    const int lhalf = (lane >> 4) * 8;
    const int z = blockIdx.z;
    const int nmat = (z == 3) ? 3 : 2;

    load_A_split(sm, A, HDIM, m0, M, tid);

#pragma unroll 1
    for (int rr = 0; rr < nmat; rr++) {
        bool is_root = (rr == 2);
        const float* B = is_root ? root1 : (w1 + (size_t)(z * 2 + rr) * HDIM * HDIM);
        load_B_h(sm, 2 * PLANE, B, tid);
        __syncthreads();

        float acc[4][4][4];
#pragma unroll
        for (int i = 0; i < 4; i++)
#pragma unroll
            for (int j = 0; j < 4; j++)
#pragma unroll
                for (int k = 0; k < 4; k++) acc[i][j][k] = 0.f;

        compute_2t(sb, wm, wn, lrow, lhalf, acc);

#pragma unroll
        for (int mf = 0; mf < 4; mf++)
#pragma unroll
            for (int nf = 0; nf < 4; nf++) {
                int r0 = m0 + wm + mf * 16 + (lane >> 2);
                int r1 = r0 + 8;
                int cl = wn + nf * 8 + (lane & 3) * 2;
                if (is_root) {
                    float b0 = bias[cl], b1v = bias[cl + 1];
                    if (r0 < M)
                        *(__half2*)(g_h1h + (size_t)r0 * HDIM + cl) =
                            __floats2half2_rn(fmaxf(acc[mf][nf][0] + b0, 0.f),
                                              fmaxf(acc[mf][nf][1] + b1v, 0.f));
                    if (r1 < M)
                        *(__half2*)(g_h1h + (size_t)r1 * HDIM + cl) =
                            __floats2half2_rn(fmaxf(acc[mf][nf][2] + b0, 0.f),
                                              fmaxf(acc[mf][nf][3] + b1v, 0.f));
                } else {
                    int r = z * 2 + rr;
                    if (r0 < M)
                        *(__half2*)(g_y1h + (size_t)r0 * (RREL * HDIM) + r * HDIM + cl) =
                            __floats2half2_rn(acc[mf][nf][0], acc[mf][nf][1]);
                    if (r1 < M)
                        *(__half2*)(g_y1h + (size_t)r1 * (RREL * HDIM) + r * HDIM + cl) =
                            __floats2half2_rn(acc[mf][nf][2], acc[mf][nf][3]);
                }
            }
        __syncthreads();
    }
}

// fused layer-2 + classifier; A exact fp16, B single fp16 -> 1 mma term.
__global__ void __launch_bounds__(256, 2)
l2_k(const __half* __restrict__ sum2, const __half* __restrict__ h1,
     const float* __restrict__ w2, const float* __restrict__ root2,
     const float* __restrict__ b2, const float* __restrict__ clsw,
     const float* __restrict__ clsb, float* __restrict__ out, int M) {
    extern __shared__ char sm[];
    const uint32_t sb = smem_u32(sm);
    const int tid = threadIdx.x;
    const int lane = tid & 31;
    const int warp = tid >> 5;
    const int wm = (warp >> 2) * 64;
    const int wn = (warp & 3) * 32;
    const int m0 = blockIdx.x * 128;
    const int lrow = lane & 15;
    const int lhalf = (lane >> 4) * 8;

    float acc[4][4][4];
#pragma unroll
    for (int i = 0; i < 4; i++)
#pragma unroll
        for (int j = 0; j < 4; j++)
#pragma unroll
            for (int k = 0; k < 4; k++) acc[i][j][k] = 0.f;

#pragma unroll 1
    for (int s = 0; s < 9; s++) {
        if (s < 8) load_A_copy(sm, sum2, RREL * HDIM, s * HDIM, m0, M, tid);
        else       load_A_copy(sm, h1, HDIM, 0, m0, M, tid);
        load_B_h(sm, PLANE, (s < 8) ? (w2 + (size_t)s * HDIM * HDIM) : root2, tid);
        __syncthreads();
        compute_1t(sb, wm, wn, lrow, lhalf, acc);
        __syncthreads();
    }

    float* redA = (float*)sm;
    float* redB = (float*)sm + 512;
#pragma unroll
    for (int mf = 0; mf < 4; mf++) {
        float p0a = 0.f, p0b = 0.f, p1a = 0.f, p1b = 0.f;
#pragma unroll
        for (int nf = 0; nf < 4; nf++) {
            int cl = wn + nf * 8 + (lane & 3) * 2;
            float b0 = b2[cl], b1v = b2[cl + 1];
            float w00 = clsw[cl * 2], w01 = clsw[cl * 2 + 1];
            float w10 = clsw[(cl + 1) * 2], w11 = clsw[(cl + 1) * 2 + 1];
            float v0 = fmaxf(acc[mf][nf][0] + b0, 0.f);
            float v1 = fmaxf(acc[mf][nf][1] + b1v, 0.f);
            float v2 = fmaxf(acc[mf][nf][2] + b0, 0.f);
            float v3 = fmaxf(acc[mf][nf][3] + b1v, 0.f);
            p0a += v0 * w00 + v1 * w10; p0b += v0 * w01 + v1 * w11;
            p1a += v2 * w00 + v3 * w10; p1b += v2 * w01 + v3 * w11;
        }
#pragma unroll
        for (int o = 1; o <= 2; o <<= 1) {
            p0a += __shfl_xor_sync(0xffffffffu, p0a, o);
            p0b += __shfl_xor_sync(0xffffffffu, p0b, o);
            p1a += __shfl_xor_sync(0xffffffffu, p1a, o);
            p1b += __shfl_xor_sync(0xffffffffu, p1b, o);
        }
        if ((lane & 3) == 0) {
            int r0 = wm + mf * 16 + (lane >> 2);
            redA[r0 * 4 + (warp & 3)] = p0a;
            redB[r0 * 4 + (warp & 3)] = p0b;
            redA[(r0 + 8) * 4 + (warp & 3)] = p1a;
            redB[(r0 + 8) * 4 + (warp & 3)] = p1b;
        }
    }
    __syncthreads();
    if (tid < 128) {
        int gr = m0 + tid;
        if (gr < M) {
            float o0 = redA[tid * 4] + redA[tid * 4 + 1] + redA[tid * 4 + 2] + redA[tid * 4 + 3] + clsb[0];
            float o1 = redB[tid * 4] + redB[tid * 4 + 1] + redB[tid * 4 + 2] + redB[tid * 4 + 3] + clsb[1];
            out[gr * 2 + 0] = o0;
            out[gr * 2 + 1] = o1;
        }
    }
}

// ---------------- driver: fork/join two independent chains --------------------
static cudaStream_t g_s2 = nullptr;
static cudaEvent_t  g_evF = nullptr, g_evJ = nullptr;

extern "C" void kernel_launch(void* const* d_in, const int* in_sizes, int n_in,
                              void* d_out, int out_size) {
    const float* x     = (const float*)d_in[0];
    const int*   er    = (const int*)d_in[1];
    const int*   ea    = (const int*)d_in[2];
    const int*   et    = (const int*)d_in[3];
    const float* mlp_w = (const float*)d_in[4];
    const float* mlp_b = (const float*)d_in[5];
    const float* w1    = (const float*)d_in[6];
    const float* root1 = (const float*)d_in[7];
    const float* b1    = (const float*)d_in[8];
    const float* w2    = (const float*)d_in[9];
    const float* root2 = (const float*)d_in[10];
    const float* b2    = (const float*)d_in[11];
    const float* cls_w = (const float*)d_in[12];
    const float* cls_b = (const float*)d_in[13];
    int E = in_sizes[1];
    float* out = (float*)d_out;

    if (!g_s2) {   // first call is the uncaptured correctness run
        cudaStreamCreateWithFlags(&g_s2, cudaStreamNonBlocking);
        cudaEventCreateWithFlags(&g_evF, cudaEventDisableTiming);
        cudaEventCreateWithFlags(&g_evJ, cudaEventDisableTiming);
    }

    void *pH0, *pH1h, *pS2h;
    cudaGetSymbolAddress(&pH0, g_h0);
    cudaGetSymbolAddress(&pH1h, g_h1h);
    cudaGetSymbolAddress(&pS2h, g_sum2h);

    cudaFuncSetAttribute(y1root_k, cudaFuncAttributeMaxDynamicSharedMemorySize, SMEM_Y1);
    cudaFuncSetAttribute(l2_k, cudaFuncAttributeMaxDynamicSharedMemorySize, SMEM_L2);

    const int GB = (NREPO + 127) / 128;   // 235

    // ---- fork: dense front (independent of CSR) on side stream ----
    cudaEventRecord(g_evF, 0);
    cudaStreamWaitEvent(g_s2, g_evF, 0);
    mlpuroot_k<<<MBLKS + UBLKS, 256, 0, g_s2>>>(x, mlp_w, mlp_b, root1);
    y1root_k<<<dim3(GB, 1, 4), 256, SMEM_Y1, g_s2>>>((const float*)pH0, NREPO, w1, root1, b1);
    cudaEventRecord(g_evJ, g_s2);

    // ---- CSR chain on main stream (overlaps dense front) ----
    zero_k<<<(B1 + 255) / 256, 256>>>();
    count_k<<<(E + 255) / 256, 256>>>(er, ea, et, E);
    scan_blk_all_k<<<NB1 + NB2, 1024>>>();
    scan_add_all_k<<<NB1 + NB2, 1024>>>();
    place_k<<<(E + 255) / 256, 256>>>(er, ea, et, E);

    // ---- join ----
    cudaStreamWaitEvent(0, g_evJ, 0);

    // layer-1 aggregation
    agg1_k<<<(NUSER * 16 + 255) / 256, 256>>>(b1, E);
    // layer-2 aggregation
    agg2_k<<<((size_t)B2 * 16 + 255) / 256, 256>>>();
    // fused layer-2 dense + classifier (2 blocks/SM)
    l2_k<<<GB, 256, SMEM_L2>>>(
        (const __half*)pS2h, (const __half*)pH1h, w2, root2, b2, cls_w, cls_b, out, NREPO);
}

// round 16
// speedup vs baseline: 2.1961x; 1.0943x over previous
#include <cuda_runtime.h>
#include <cuda_fp16.h>
#include <cstdint>

#define NREPO 30000
#define NUSER 70000
#define NNODE 100000
#define RREL  8
#define HDIM  128
#define B1 (NUSER * RREL)
#define B2 (NREPO * RREL)
#define NB1 ((B1 + 1023) / 1024)
#define NB2 ((B2 + 1023) / 1024)
#define EMAX 1000000

#define MBLKS ((NREPO * HDIM + 255) / 256)
#define UBLKS (HDIM / 2)
#define CBLKS ((18 * HDIM * HDIM) / 256)     // weight fp16 conversion blocks (1152)

// ---------------- scratch ----------------------------------------------------
__device__ __half g_h0h[(size_t)NREPO * HDIM];
__device__ __half g_h1h[(size_t)NNODE * HDIM];
__device__ __half g_y1h[(size_t)B2 * HDIM];
__device__ __half g_sum2h[(size_t)B2 * HDIM];
__device__ __half g_w1h[9 * HDIM * HDIM];    // w1[0..8) then root1
__device__ __half g_w2h[9 * HDIM * HDIM];    // w2[0..8) then root2
__device__ float  g_uroot[HDIM];
__device__ int    g_cnt1[B1], g_off1[B1], g_cur1[B1], g_bsum1[NB1];
__device__ int    g_cnt2[B2], g_off2[B2], g_cur2[B2], g_bsum2[NB2];
__device__ int    g_perm1[EMAX];
__device__ int    g_perm2[EMAX];

// ---------------- CSR-side kernels -------------------------------------------
__global__ void zero_k() {
    int i = blockIdx.x * blockDim.x + threadIdx.x;
    if (i < B1) g_cnt1[i] = 0;
    if (i < B2) g_cnt2[i] = 0;
}

__global__ void count_k(const int* __restrict__ er, const int* __restrict__ ea,
                        const int* __restrict__ et, int E) {
    int e = blockIdx.x * blockDim.x + threadIdx.x;
    if (e >= E) return;
    atomicAdd(&g_cnt1[ea[e] * RREL + et[e]], 1);
    atomicAdd(&g_cnt2[er[e] * RREL + et[e]], 1);
}

__global__ void scan_blk_all_k() {
    __shared__ int s[1024];
    int t = threadIdx.x;
    bool first = blockIdx.x < NB1;
    int blk = first ? blockIdx.x : blockIdx.x - NB1;
    const int* cnt = first ? g_cnt1 : g_cnt2;
    int* off = first ? g_off1 : g_off2;
    int* bsum = first ? g_bsum1 : g_bsum2;
    int n = first ? B1 : B2;
    int i = blk * 1024 + t;
    int v = (i < n) ? cnt[i] : 0;
    s[t] = v;
    __syncthreads();
#pragma unroll
    for (int d = 1; d < 1024; d <<= 1) {
        int u = (t >= d) ? s[t - d] : 0;
        __syncthreads();
        s[t] += u;
        __syncthreads();
    }
    if (i < n) off[i] = s[t] - v;
    if (t == 1023) bsum[blk] = s[1023];
}

__global__ void scan_add_all_k() {
    int t = threadIdx.x;
    bool first = blockIdx.x < NB1;
    int blk = first ? blockIdx.x : blockIdx.x - NB1;
    const int* bsum = first ? g_bsum1 : g_bsum2;

    int partial = 0;
    for (int i = t; i < blk; i += 1024) partial += bsum[i];
#pragma unroll
    for (int d = 16; d; d >>= 1) partial += __shfl_xor_sync(0xffffffffu, partial, d);
    __shared__ int red[32];
    if ((t & 31) == 0) red[t >> 5] = partial;
    __syncthreads();
    __shared__ int base;
    if (t == 0) {
        int b = 0;
#pragma unroll
        for (int w = 0; w < 32; w++) b += red[w];
        base = b;
    }
    __syncthreads();
    int bs = base;

    int i = blk * 1024 + t;
    if (first) {
        if (i < B1) {
            int o = g_off1[i] + bs;
            g_off1[i] = o;
            g_cur1[i] = o;
        }
    } else {
        if (i < B2) {
            int o = g_off2[i] + bs;
            g_off2[i] = o;
            g_cur2[i] = o;
        }
    }
}

__global__ void place_k(const int* __restrict__ er, const int* __restrict__ ea,
                        const int* __restrict__ et, int E) {
    int e = blockIdx.x * blockDim.x + threadIdx.x;
    if (e >= E) return;
    int repo = er[e], actor = ea[e], t = et[e];
    int p1 = atomicAdd(&g_cur1[actor * RREL + t], 1);
    g_perm1[p1] = repo * RREL + t;
    int p2 = atomicAdd(&g_cur2[repo * RREL + t], 1);
    g_perm2[p2] = actor;
}

// ---------------- dense-front: mlp | uroot | weight fp16 conversion ----------
__global__ void mlpuroot_k(const float* __restrict__ x, const float* __restrict__ mlp_w,
                           const float* __restrict__ mlp_b, const float* __restrict__ root1,
                           const float* __restrict__ w1, const float* __restrict__ w2,
                           const float* __restrict__ root2) {
    int bx = blockIdx.x;
    int tid = threadIdx.x;
    if (bx < MBLKS) {
        int g = bx * 256 + tid;
        if (g >= NREPO * HDIM) return;
        int n = g >> 7, o = g & 127;
        float acc = mlp_b[o];
#pragma unroll
        for (int k = 0; k < 8; k++)
            acc = fmaf(__ldg(&x[n * 8 + k]), __ldg(&mlp_w[k * HDIM + o]), acc);
        g_h0h[g] = __float2half_rn(fmaxf(acc, 0.f));
        return;
    }
    bx -= MBLKS;
    if (bx < UBLKS) {
        int half = tid >> 7;
        int k = tid & 127;
        int o = bx * 2 + half;
        float v = fmaxf(mlp_b[k], 0.f) * root1[k * HDIM + o];
#pragma unroll
        for (int d = 16; d; d >>= 1) v += __shfl_xor_sync(0xffffffffu, v, d);
        __shared__ float s[8];
        int w = tid >> 5;
        if ((tid & 31) == 0) s[w] = v;
        __syncthreads();
        if (k == 0) g_uroot[o] = s[half * 4] + s[half * 4 + 1] + s[half * 4 + 2] + s[half * 4 + 3];
        return;
    }
    bx -= UBLKS;
    {   // weight conversion: 18 * 16384 elements
        int idx = bx * 256 + tid;
        const int MAT = HDIM * HDIM;        // 16384
        if (idx < 9 * MAT) {
            float v = (idx < 8 * MAT) ? w1[idx] : root1[idx - 8 * MAT];
            g_w1h[idx] = __float2half_rn(v);
        } else {
            int j = idx - 9 * MAT;
            float v = (j < 8 * MAT) ? w2[j] : root2[j - 8 * MAT];
            g_w2h[j] = __float2half_rn(v);
        }
    }
}

// ---------------- aggregations ------------------------------------------------
__global__ void agg1_k(const float* __restrict__ b1, int E) {
    int hw = (blockIdx.x * blockDim.x + threadIdx.x) >> 4;
    int lane = threadIdx.x & 31;
    int lane16 = lane & 15;
    unsigned seg = 0xFFFFu << (lane & 16);
    if (hw >= NUSER) return;
    float invreg = 0.f;
    if (lane16 < RREL) {
        int d = g_cnt1[hw * RREL + lane16];
        invreg = d ? 1.0f / (float)d : 0.f;
    }
    int start = g_off1[hw * RREL];
    int end = (hw * RREL + RREL < B1) ? g_off1[hw * RREL + RREL] : E;

    float a0, a1, a2, a3, a4, a5, a6, a7;
    {
        float4 ua = *(const float4*)(g_uroot + lane16 * 8);
        float4 ub = *(const float4*)(g_uroot + lane16 * 8 + 4);
        a0 = ua.x; a1 = ua.y; a2 = ua.z; a3 = ua.w;
        a4 = ub.x; a5 = ub.y; a6 = ub.z; a7 = ub.w;
    }

#define ACC1(u, iv) { \
        float2 f0 = __half22float2(((const __half2*)&(u))[0]); \
        float2 f1 = __half22float2(((const __half2*)&(u))[1]); \
        float2 f2 = __half22float2(((const __half2*)&(u))[2]); \
        float2 f3 = __half22float2(((const __half2*)&(u))[3]); \
        a0 = fmaf(f0.x, (iv), a0); a1 = fmaf(f0.y, (iv), a1); \
        a2 = fmaf(f1.x, (iv), a2); a3 = fmaf(f1.y, (iv), a3); \
        a4 = fmaf(f2.x, (iv), a4); a5 = fmaf(f2.y, (iv), a5); \
        a6 = fmaf(f3.x, (iv), a6); a7 = fmaf(f3.y, (iv), a7); }

    int j = start;
    for (; j + 4 <= end; j += 4) {
        int p0 = __ldg(g_perm1 + j),     p1 = __ldg(g_perm1 + j + 1);
        int p2 = __ldg(g_perm1 + j + 2), p3 = __ldg(g_perm1 + j + 3);
        uint4 u0 = *(const uint4*)(g_y1h + (((size_t)p0) << 7) + lane16 * 8);
        uint4 u1 = *(const uint4*)(g_y1h + (((size_t)p1) << 7) + lane16 * 8);
        uint4 u2 = *(const uint4*)(g_y1h + (((size_t)p2) << 7) + lane16 * 8);
        uint4 u3 = *(const uint4*)(g_y1h + (((size_t)p3) << 7) + lane16 * 8);
        float iv0 = __shfl_sync(seg, invreg, (p0 & 7) | (lane & 16));
        float iv1 = __shfl_sync(seg, invreg, (p1 & 7) | (lane & 16));
        float iv2 = __shfl_sync(seg, invreg, (p2 & 7) | (lane & 16));
        float iv3 = __shfl_sync(seg, invreg, (p3 & 7) | (lane & 16));
        ACC1(u0, iv0) ACC1(u1, iv1) ACC1(u2, iv2) ACC1(u3, iv3)
    }
    for (; j < end; j++) {
        int p0 = __ldg(g_perm1 + j);
        uint4 u0 = *(const uint4*)(g_y1h + (((size_t)p0) << 7) + lane16 * 8);
        float iv0 = __shfl_sync(seg, invreg, (p0 & 7) | (lane & 16));
        ACC1(u0, iv0)
    }
#undef ACC1

    float4 ba = *(const float4*)(b1 + lane16 * 8);
    float4 bb = *(const float4*)(b1 + lane16 * 8 + 4);
    uint4 pk;
    __half2 h0 = __floats2half2_rn(fmaxf(a0 + ba.x, 0.f), fmaxf(a1 + ba.y, 0.f));
    __half2 h1 = __floats2half2_rn(fmaxf(a2 + ba.z, 0.f), fmaxf(a3 + ba.w, 0.f));
    __half2 h2 = __floats2half2_rn(fmaxf(a4 + bb.x, 0.f), fmaxf(a5 + bb.y, 0.f));
    __half2 h3 = __floats2half2_rn(fmaxf(a6 + bb.z, 0.f), fmaxf(a7 + bb.w, 0.f));
    pk.x = *(unsigned*)&h0; pk.y = *(unsigned*)&h1;
    pk.z = *(unsigned*)&h2; pk.w = *(unsigned*)&h3;
    *(uint4*)(g_h1h + (((size_t)(NREPO + hw)) << 7) + lane16 * 8) = pk;
}

__global__ void agg2_k() {
    int bin = (blockIdx.x * blockDim.x + threadIdx.x) >> 4;
    int lane16 = threadIdx.x & 15;
    if (bin >= B2) return;
    int deg = g_cnt2[bin];
    int start = g_off2[bin];
    float a0 = 0.f, a1 = 0.f, a2 = 0.f, a3 = 0.f, a4 = 0.f, a5 = 0.f, a6 = 0.f, a7 = 0.f;
#define ACC2(u) { \
        float2 f0 = __half22float2(((const __half2*)&(u))[0]); \
        float2 f1 = __half22float2(((const __half2*)&(u))[1]); \
        float2 f2 = __half22float2(((const __half2*)&(u))[2]); \
        float2 f3 = __half22float2(((const __half2*)&(u))[3]); \
        a0 += f0.x; a1 += f0.y; a2 += f1.x; a3 += f1.y; \
        a4 += f2.x; a5 += f2.y; a6 += f3.x; a7 += f3.y; }
    int j = 0;
    for (; j + 4 <= deg; j += 4) {
        int c0 = __ldg(g_perm2 + start + j);
        int c1 = __ldg(g_perm2 + start + j + 1);
        int c2 = __ldg(g_perm2 + start + j + 2);
        int c3 = __ldg(g_perm2 + start + j + 3);
        uint4 u0 = *(const uint4*)(g_h1h + (((size_t)(NREPO + c0)) << 7) + lane16 * 8);
        uint4 u1 = *(const uint4*)(g_h1h + (((size_t)(NREPO + c1)) << 7) + lane16 * 8);
        uint4 u2 = *(const uint4*)(g_h1h + (((size_t)(NREPO + c2)) << 7) + lane16 * 8);
        uint4 u3 = *(const uint4*)(g_h1h + (((size_t)(NREPO + c3)) << 7) + lane16 * 8);
        ACC2(u0) ACC2(u1) ACC2(u2) ACC2(u3)
    }
    for (; j < deg; j++) {
        int c0 = __ldg(g_perm2 + start + j);
        uint4 u0 = *(const uint4*)(g_h1h + (((size_t)(NREPO + c0)) << 7) + lane16 * 8);
        ACC2(u0)
    }
#undef ACC2
    float inv = deg ? 1.0f / (float)deg : 0.f;
    uint4 pk;
    __half2 h0 = __floats2half2_rn(a0 * inv, a1 * inv);
    __half2 h1 = __floats2half2_rn(a2 * inv, a3 * inv);
    __half2 h2 = __floats2half2_rn(a4 * inv, a5 * inv);
    __half2 h3 = __floats2half2_rn(a6 * inv, a7 * inv);
    pk.x = *(unsigned*)&h0; pk.y = *(unsigned*)&h1;
    pk.z = *(unsigned*)&h2; pk.w = *(unsigned*)&h3;
    *(uint4*)(g_sum2h + ((size_t)bin << 7) + lane16 * 8) = pk;
}

// ================= fp16 tensor-core GEMM pieces ==============================
#define PITCH 136
#define PLANE 34816                 // bytes per 128 x PITCH fp16 plane
#define SMEM_GG (2 * PLANE + 128)   // A, B (both kernels)

__device__ __forceinline__ uint32_t smem_u32(const void* p) {
    uint32_t a;
    asm("{ .reg .u64 t; cvta.to.shared.u64 t, %1; cvt.u32.u64 %0, t; }" : "=r"(a) : "l"(p));
    return a;
}

__device__ __forceinline__ void ldsm_x4(unsigned r[4], uint32_t addr) {
    asm volatile("ldmatrix.sync.aligned.m8n8.x4.shared.b16 {%0,%1,%2,%3}, [%4];"
                 : "=r"(r[0]), "=r"(r[1]), "=r"(r[2]), "=r"(r[3]) : "r"(addr));
}

__device__ __forceinline__ void ldsm_x4_t(unsigned r[4], uint32_t addr) {
    asm volatile("ldmatrix.sync.aligned.m8n8.x4.trans.shared.b16 {%0,%1,%2,%3}, [%4];"
                 : "=r"(r[0]), "=r"(r[1]), "=r"(r[2]), "=r"(r[3]) : "r"(addr));
}

__device__ __forceinline__ void mma_f16(float c[4], const unsigned a[4], const unsigned* b) {
    asm volatile(
        "mma.sync.aligned.m16n8k16.row.col.f32.f16.f16.f32 "
        "{%0,%1,%2,%3}, {%4,%5,%6,%7}, {%8,%9}, {%0,%1,%2,%3};"
        : "+f"(c[0]), "+f"(c[1]), "+f"(c[2]), "+f"(c[3])
        : "r"(a[0]), "r"(a[1]), "r"(a[2]), "r"(a[3]), "r"(b[0]), "r"(b[1]));
}

// fp16 source -> plane copy (A at offset 0 with bounds, B at byte offset po)
__device__ __forceinline__ void load_A_copy(char* sm, const __half* __restrict__ A, int lda,
                                            int cO, int m0, int M, int tid) {
#pragma unroll
    for (int it = 0; it < 16; it++) {
        int v = tid + it * 256;
        int row = v >> 5;
        int c4 = (v & 31) * 4;
        uint2 u = make_uint2(0u, 0u);
        if (m0 + row < M) u = *(const uint2*)(A + (size_t)(m0 + row) * lda + cO + c4);
        *(uint2*)(sm + (row * PITCH + c4) * 2) = u;
    }
}

__device__ __forceinline__ void load_B_copy(char* sm, int po, const __half* __restrict__ B, int tid) {
#pragma unroll
    for (int it = 0; it < 16; it++) {
        int v = tid + it * 256;
        int row = v >> 5;
        int c4 = (v & 31) * 4;
        *(uint2*)(sm + po + (row * PITCH + c4) * 2) =
            *(const uint2*)(B + (size_t)row * 128 + c4);
    }
}

// 1-term compute: A @ B   (planes: 0=A, PLANE=B)
__device__ __forceinline__ void compute_1t(uint32_t sb, int wm, int wn, int lrow,
                                           int lhalf, float (&acc)[4][4][4]) {
#pragma unroll 1
    for (int kc = 0; kc < 8; kc++) {
        int k0 = kc * 16;
        unsigned Af[4][4], Bf[2][4];
#pragma unroll
        for (int mf = 0; mf < 4; mf++)
            ldsm_x4(Af[mf], sb + ((wm + mf * 16 + lrow) * PITCH + k0 + lhalf) * 2);
#pragma unroll
        for (int np = 0; np < 2; np++)
            ldsm_x4_t(Bf[np], sb + ((k0 + lrow) * PITCH + wn + np * 16 + lhalf) * 2 + PLANE);
#pragma unroll
        for (int mf = 0; mf < 4; mf++)
#pragma unroll
            for (int nf = 0; nf < 4; nf++)
                mma_f16(acc[mf][nf], Af[mf], &Bf[nf >> 1][(nf & 1) * 2]);
    }
}

// y1 + root1 fused: grid z in [0,4). z<3: relations {2z, 2z+1}.
// z==3: relations {6, 7} then root1 (bias+relu -> h1h).
__global__ void __launch_bounds__(256, 2)
y1root_k(int M, const float* __restrict__ bias) {
    extern __shared__ char sm[];
    const uint32_t sb = smem_u32(sm);
    const int tid = threadIdx.x;
    const int lane = tid & 31;
    const int warp = tid >> 5;
    const int wm = (warp >> 2) * 64;
    const int wn = (warp & 3) * 32;
    const int m0 = blockIdx.x * 128;
    const int lrow = lane & 15;
    const int lhalf = (lane >> 4) * 8;
    const int z = blockIdx.z;
    const int nmat = (z == 3) ? 3 : 2;

    load_A_copy(sm, g_h0h, HDIM, 0, m0, M, tid);

#pragma unroll 1
    for (int rr = 0; rr < nmat; rr++) {
        bool is_root = (rr == 2);
        int matIdx = is_root ? 8 : (z * 2 + rr);
        load_B_copy(sm, PLANE, g_w1h + (size_t)matIdx * HDIM * HDIM, tid);
        __syncthreads();

        float acc[4][4][4];
#pragma unroll
        for (int i = 0; i < 4; i++)
#pragma unroll
            for (int j = 0; j < 4; j++)
#pragma unroll
                for (int k = 0; k < 4; k++) acc[i][j][k] = 0.f;

        compute_1t(sb, wm, wn, lrow, lhalf, acc);

#pragma unroll
        for (int mf = 0; mf < 4; mf++)
#pragma unroll
            for (int nf = 0; nf < 4; nf++) {
                int r0 = m0 + wm + mf * 16 + (lane >> 2);
                int r1 = r0 + 8;
                int cl = wn + nf * 8 + (lane & 3) * 2;
                if (is_root) {
                    float b0 = bias[cl], b1v = bias[cl + 1];
                    if (r0 < M)
                        *(__half2*)(g_h1h + (size_t)r0 * HDIM + cl) =
                            __floats2half2_rn(fmaxf(acc[mf][nf][0] + b0, 0.f),
                                              fmaxf(acc[mf][nf][1] + b1v, 0.f));
                    if (r1 < M)
                        *(__half2*)(g_h1h + (size_t)r1 * HDIM + cl) =
                            __floats2half2_rn(fmaxf(acc[mf][nf][2] + b0, 0.f),
                                              fmaxf(acc[mf][nf][3] + b1v, 0.f));
                } else {
                    int r = z * 2 + rr;
                    if (r0 < M)
                        *(__half2*)(g_y1h + (size_t)r0 * (RREL * HDIM) + r * HDIM + cl) =
                            __floats2half2_rn(acc[mf][nf][0], acc[mf][nf][1]);
                    if (r1 < M)
                        *(__half2*)(g_y1h + (size_t)r1 * (RREL * HDIM) + r * HDIM + cl) =
                            __floats2half2_rn(acc[mf][nf][2], acc[mf][nf][3]);
                }
            }
        __syncthreads();
    }
}

// fused layer-2 + classifier; A exact fp16, B pre-converted fp16 -> 1 term.
__global__ void __launch_bounds__(256, 2)
l2_k(const __half* __restrict__ sum2, const __half* __restrict__ h1,
     const float* __restrict__ b2, const float* __restrict__ clsw,
     const float* __restrict__ clsb, float* __restrict__ out, int M) {
    extern __shared__ char sm[];
    const uint32_t sb = smem_u32(sm);
    const int tid = threadIdx.x;
    const int lane = tid & 31;
    const int warp = tid >> 5;
    const int wm = (warp >> 2) * 64;
    const int wn = (warp & 3) * 32;
    const int m0 = blockIdx.x * 128;
    const int lrow = lane & 15;
    const int lhalf = (lane >> 4) * 8;

    float acc[4][4][4];
#pragma unroll
    for (int i = 0; i < 4; i++)
#pragma unroll
        for (int j = 0; j < 4; j++)
#pragma unroll
            for (int k = 0; k < 4; k++) acc[i][j][k] = 0.f;

#pragma unroll 1
    for (int s = 0; s < 9; s++) {
        if (s < 8) load_A_copy(sm, sum2, RREL * HDIM, s * HDIM, m0, M, tid);
        else       load_A_copy(sm, h1, HDIM, 0, m0, M, tid);
        load_B_copy(sm, PLANE, g_w2h + (size_t)s * HDIM * HDIM, tid);
        __syncthreads();
        compute_1t(sb, wm, wn, lrow, lhalf, acc);
        __syncthreads();
    }

    float* redA = (float*)sm;
    float* redB = (float*)sm + 512;
#pragma unroll
    for (int mf = 0; mf < 4; mf++) {
        float p0a = 0.f, p0b = 0.f, p1a = 0.f, p1b = 0.f;
#pragma unroll
        for (int nf = 0; nf < 4; nf++) {
            int cl = wn + nf * 8 + (lane & 3) * 2;
            float b0 = b2[cl], b1v = b2[cl + 1];
            float w00 = clsw[cl * 2], w01 = clsw[cl * 2 + 1];
            float w10 = clsw[(cl + 1) * 2], w11 = clsw[(cl + 1) * 2 + 1];
            float v0 = fmaxf(acc[mf][nf][0] + b0, 0.f);
            float v1 = fmaxf(acc[mf][nf][1] + b1v, 0.f);
            float v2 = fmaxf(acc[mf][nf][2] + b0, 0.f);
            float v3 = fmaxf(acc[mf][nf][3] + b1v, 0.f);
            p0a += v0 * w00 + v1 * w10; p0b += v0 * w01 + v1 * w11;
            p1a += v2 * w00 + v3 * w10; p1b += v2 * w01 + v3 * w11;
        }
#pragma unroll
        for (int o = 1; o <= 2; o <<= 1) {
            p0a += __shfl_xor_sync(0xffffffffu, p0a, o);
            p0b += __shfl_xor_sync(0xffffffffu, p0b, o);
            p1a += __shfl_xor_sync(0xffffffffu, p1a, o);
            p1b += __shfl_xor_sync(0xffffffffu, p1b, o);
        }
        if ((lane & 3) == 0) {
            int r0 = wm + mf * 16 + (lane >> 2);
            redA[r0 * 4 + (warp & 3)] = p0a;
            redB[r0 * 4 + (warp & 3)] = p0b;
            redA[(r0 + 8) * 4 + (warp & 3)] = p1a;
            redB[(r0 + 8) * 4 + (warp & 3)] = p1b;
        }
    }
    __syncthreads();
    if (tid < 128) {
        int gr = m0 + tid;
        if (gr < M) {
            float o0 = redA[tid * 4] + redA[tid * 4 + 1] + redA[tid * 4 + 2] + redA[tid * 4 + 3] + clsb[0];
            float o1 = redB[tid * 4] + redB[tid * 4 + 1] + redB[tid * 4 + 2] + redB[tid * 4 + 3] + clsb[1];
            out[gr * 2 + 0] = o0;
            out[gr * 2 + 1] = o1;
        }
    }
}

// ---------------- driver: fork/join two independent chains --------------------
static cudaStream_t g_s2 = nullptr;
static cudaEvent_t  g_evF = nullptr, g_evJ = nullptr;

extern "C" void kernel_launch(void* const* d_in, const int* in_sizes, int n_in,
                              void* d_out, int out_size) {
    const float* x     = (const float*)d_in[0];
    const int*   er    = (const int*)d_in[1];
    const int*   ea    = (const int*)d_in[2];
    const int*   et    = (const int*)d_in[3];
    const float* mlp_w = (const float*)d_in[4];
    const float* mlp_b = (const float*)d_in[5];
    const float* w1    = (const float*)d_in[6];
    const float* root1 = (const float*)d_in[7];
    const float* b1    = (const float*)d_in[8];
    const float* w2    = (const float*)d_in[9];
    const float* root2 = (const float*)d_in[10];
    const float* b2    = (const float*)d_in[11];
    const float* cls_w = (const float*)d_in[12];
    const float* cls_b = (const float*)d_in[13];
    int E = in_sizes[1];
    float* out = (float*)d_out;

    if (!g_s2) {   // first call is the uncaptured correctness run
        cudaStreamCreateWithFlags(&g_s2, cudaStreamNonBlocking);
        cudaEventCreateWithFlags(&g_evF, cudaEventDisableTiming);
        cudaEventCreateWithFlags(&g_evJ, cudaEventDisableTiming);
    }

    void *pH1h, *pS2h;
    cudaGetSymbolAddress(&pH1h, g_h1h);
    cudaGetSymbolAddress(&pS2h, g_sum2h);

    cudaFuncSetAttribute(y1root_k, cudaFuncAttributeMaxDynamicSharedMemorySize, SMEM_GG);
    cudaFuncSetAttribute(l2_k, cudaFuncAttributeMaxDynamicSharedMemorySize, SMEM_GG);

    const int GB = (NREPO + 127) / 128;   // 235

    // ---- fork: dense front (independent of CSR) on side stream ----
    cudaEventRecord(g_evF, 0);
    cudaStreamWaitEvent(g_s2, g_evF, 0);
    mlpuroot_k<<<MBLKS + UBLKS + CBLKS, 256, 0, g_s2>>>(x, mlp_w, mlp_b, root1, w1, w2, root2);
    y1root_k<<<dim3(GB, 1, 4), 256, SMEM_GG, g_s2>>>(NREPO, b1);
    cudaEventRecord(g_evJ, g_s2);

    // ---- CSR chain on main stream (overlaps dense front) ----
    zero_k<<<(B1 + 255) / 256, 256>>>();
    count_k<<<(E + 255) / 256, 256>>>(er, ea, et, E);
    scan_blk_all_k<<<NB1 + NB2, 1024>>>();
    scan_add_all_k<<<NB1 + NB2, 1024>>>();
    place_k<<<(E + 255) / 256, 256>>>(er, ea, et, E);

    // ---- join ----
    cudaStreamWaitEvent(0, g_evJ, 0);

    // layer-1 aggregation
    agg1_k<<<(NUSER * 16 + 255) / 256, 256>>>(b1, E);
    // layer-2 aggregation
    agg2_k<<<((size_t)B2 * 16 + 255) / 256, 256>>>();
    // fused layer-2 dense + classifier
    l2_k<<<GB, 256, SMEM_GG>>>(
        (const __half*)pS2h, (const __half*)pH1h, b2, cls_w, cls_b, out, NREPO);
}